// round 3
// baseline (speedup 1.0000x reference)
#include <cuda_runtime.h>
#include <math.h>

#define DD 256
#define SS 256
#define BB 1024
#define NB 64

// Scratch (device globals; no allocation allowed)
__device__ float d_L[(size_t)SS * DD * DD];          // 64 MB: Sigma -> L (lower valid)
__device__ float d_invDiag[(size_t)SS * 4 * NB * NB]; // 16.8 MB: inv of diag 64x64 blocks
__device__ float d_ridge[SS];
__device__ float d_logdet[SS];

// ---------------------------------------------------------------------------
// Kernel 1: ridge[s] = 0.01 * ||sp_s||_F^2 / D   (= 0.01 * trace(sp^T sp)/D)
// ---------------------------------------------------------------------------
__global__ __launch_bounds__(256) void ridge_kernel(const float* __restrict__ sp) {
    const int s = blockIdx.x;
    const float* A = sp + (size_t)s * DD * DD;
    float acc = 0.f;
    for (int i = threadIdx.x; i < DD * DD; i += 256) { float v = A[i]; acc += v * v; }
    __shared__ float red[256];
    red[threadIdx.x] = acc; __syncthreads();
    for (int o = 128; o > 0; o >>= 1) {
        if (threadIdx.x < o) red[threadIdx.x] += red[threadIdx.x + o];
        __syncthreads();
    }
    if (threadIdx.x == 0) d_ridge[s] = 0.01f * red[0] / (float)DD;
}

// ---------------------------------------------------------------------------
// Kernel 2: Sigma_s = sp^T sp + ridge*I, lower-triangle tiles only (10 tiles).
// C[d][e] = sum_k A[k][d] * A[k][e]
// ---------------------------------------------------------------------------
__global__ __launch_bounds__(256) void syrk_kernel(const float* __restrict__ sp) {
    const int t = blockIdx.x;                               // 0..9 lower tiles
    const int ti = (int)((sqrtf(8.0f * t + 1.0f) - 1.0f) * 0.5f);
    const int tj = t - (ti * (ti + 1)) / 2;
    const int s = blockIdx.y;
    const float* A = sp + (size_t)s * DD * DD;
    float* C = d_L + (size_t)s * DD * DD;

    __shared__ float sA[16 * 65];
    __shared__ float sB[16 * 65];
    const int tid = threadIdx.x, tx = tid & 15, ty = tid >> 4;

    float acc[4][4];
#pragma unroll
    for (int r = 0; r < 4; r++)
#pragma unroll
        for (int c = 0; c < 4; c++) acc[r][c] = 0.f;

    for (int k0 = 0; k0 < DD; k0 += 16) {
        for (int idx = tid; idx < 1024; idx += 256) {
            int kk = idx >> 6, c = idx & 63;
            sA[kk * 65 + c] = A[(size_t)(k0 + kk) * DD + ti * NB + c];
            sB[kk * 65 + c] = A[(size_t)(k0 + kk) * DD + tj * NB + c];
        }
        __syncthreads();
#pragma unroll
        for (int kk = 0; kk < 16; kk++) {
            float a0 = sA[kk * 65 + ty * 4 + 0];
            float a1 = sA[kk * 65 + ty * 4 + 1];
            float a2 = sA[kk * 65 + ty * 4 + 2];
            float a3 = sA[kk * 65 + ty * 4 + 3];
            float b0 = sB[kk * 65 + tx * 4 + 0];
            float b1 = sB[kk * 65 + tx * 4 + 1];
            float b2 = sB[kk * 65 + tx * 4 + 2];
            float b3 = sB[kk * 65 + tx * 4 + 3];
            acc[0][0] += a0 * b0; acc[0][1] += a0 * b1; acc[0][2] += a0 * b2; acc[0][3] += a0 * b3;
            acc[1][0] += a1 * b0; acc[1][1] += a1 * b1; acc[1][2] += a1 * b2; acc[1][3] += a1 * b3;
            acc[2][0] += a2 * b0; acc[2][1] += a2 * b1; acc[2][2] += a2 * b2; acc[2][3] += a2 * b3;
            acc[3][0] += a3 * b0; acc[3][1] += a3 * b1; acc[3][2] += a3 * b2; acc[3][3] += a3 * b3;
        }
        __syncthreads();
    }
    if (ti == tj) {
        float ridge = d_ridge[s];
#pragma unroll
        for (int r = 0; r < 4; r++)
#pragma unroll
            for (int c = 0; c < 4; c++)
                if (ty * 4 + r == tx * 4 + c) acc[r][c] += ridge;
    }
#pragma unroll
    for (int r = 0; r < 4; r++) {
        float4 v = make_float4(acc[r][0], acc[r][1], acc[r][2], acc[r][3]);
        *(float4*)&C[(size_t)(ti * NB + ty * 4 + r) * DD + tj * NB + tx * 4] = v;
    }
}

// ---------------------------------------------------------------------------
// Kernel 3: per-s blocked Cholesky (right-looking, NB=64, panel in smem),
// diag-block inverses, logdet. One CTA (256 threads) per s.
// dyn smem: sP 256*65 + sI 64*65 floats = 83,200 B
// ---------------------------------------------------------------------------
__global__ __launch_bounds__(256) void chol_kernel() {
    extern __shared__ float sm[];
    float* sP = sm;               // 256*65
    float* sI = sm + 256 * 65;    // 64*65
    __shared__ float sLd;
    const int s = blockIdx.x;
    const int tid = threadIdx.x;
    float* L = d_L + (size_t)s * DD * DD;
    if (tid == 0) sLd = 0.f;

    for (int p = 0; p < 4; p++) {
        const int r0 = p * NB;
        const int nrows = DD - r0;
        // load panel (cols p-block, rows r0..255)
        for (int idx = tid; idx < nrows * NB; idx += 256)
            sP[(idx >> 6) * 65 + (idx & 63)] = L[(size_t)(r0 + (idx >> 6)) * DD + r0 + (idx & 63)];
        __syncthreads();

        // unblocked factor of whole panel; keep diagonal UNSQRT'd during loop
        for (int j = 0; j < NB; j++) {
            float dj = sP[j * 65 + j];        // safe: written last at step j-1 update (synced)
            float rs = 1.0f / sqrtf(dj);
            if (tid == 0) sLd += logf(dj);    // logdet = sum log d_j = 2 sum log L_jj
            for (int r = j + 1 + tid; r < nrows; r += 256) sP[r * 65 + j] *= rs;
            __syncthreads();
            int c = j + 1 + (tid & 63);
            if (c < NB) {
                float lc = sP[c * 65 + j];
                for (int r = j + 1 + (tid >> 6); r < nrows; r += 4)
                    sP[r * 65 + c] -= sP[r * 65 + j] * lc;
            }
            __syncthreads();
        }
        // fix diagonal to sqrt
        if (tid < NB) sP[tid * 65 + tid] = sqrtf(sP[tid * 65 + tid]);
        __syncthreads();

        // write panel back as L
        for (int idx = tid; idx < nrows * NB; idx += 256)
            L[(size_t)(r0 + (idx >> 6)) * DD + r0 + (idx & 63)] = sP[(idx >> 6) * 65 + (idx & 63)];

        // invert diag block (forward solve per column, thread per column)
        if (tid < NB) {
            int c = tid;
            for (int r = 0; r < NB; r++) {
                float v = (r == c) ? 1.f : 0.f;
                for (int k = c; k < r; k++) v -= sP[r * 65 + k] * sI[k * 65 + c];
                sI[r * 65 + c] = (r < c) ? 0.f : v / sP[r * 65 + r];
            }
        }
        __syncthreads();
        for (int idx = tid; idx < NB * NB; idx += 256)
            d_invDiag[((size_t)s * 4 + p) * (NB * NB) + idx] = sI[(idx >> 6) * 65 + (idx & 63)];

        // trailing update in gmem: Trail -= L21 L21^T  (full squares; garbage upper unread)
        const int nt = 3 - p;
        const int tx = tid & 15, ty = tid >> 4;
        for (int ti2 = 0; ti2 < nt; ti2++)
            for (int tj2 = 0; tj2 < nt; tj2++) {
                int lr = NB + ti2 * NB + ty * 4;
                int lc = NB + tj2 * NB + tx * 4;
                float accm[4][4];
#pragma unroll
                for (int r = 0; r < 4; r++) {
                    float4 v = *(float4*)&L[(size_t)(r0 + lr + r) * DD + r0 + lc];
                    accm[r][0] = v.x; accm[r][1] = v.y; accm[r][2] = v.z; accm[r][3] = v.w;
                }
#pragma unroll 4
                for (int k = 0; k < NB; k++) {
                    float a0 = sP[(lr + 0) * 65 + k];
                    float a1 = sP[(lr + 1) * 65 + k];
                    float a2 = sP[(lr + 2) * 65 + k];
                    float a3 = sP[(lr + 3) * 65 + k];
                    float b0 = sP[(lc + 0) * 65 + k];
                    float b1 = sP[(lc + 1) * 65 + k];
                    float b2 = sP[(lc + 2) * 65 + k];
                    float b3 = sP[(lc + 3) * 65 + k];
                    accm[0][0] -= a0 * b0; accm[0][1] -= a0 * b1; accm[0][2] -= a0 * b2; accm[0][3] -= a0 * b3;
                    accm[1][0] -= a1 * b0; accm[1][1] -= a1 * b1; accm[1][2] -= a1 * b2; accm[1][3] -= a1 * b3;
                    accm[2][0] -= a2 * b0; accm[2][1] -= a2 * b1; accm[2][2] -= a2 * b2; accm[2][3] -= a2 * b3;
                    accm[3][0] -= a3 * b0; accm[3][1] -= a3 * b1; accm[3][2] -= a3 * b2; accm[3][3] -= a3 * b3;
                }
#pragma unroll
                for (int r = 0; r < 4; r++) {
                    float4 v = make_float4(accm[r][0], accm[r][1], accm[r][2], accm[r][3]);
                    *(float4*)&L[(size_t)(r0 + lr + r) * DD + r0 + lc] = v;
                }
            }
        __syncthreads();  // all trailing reads of sP done before next panel load
    }
    if (tid == 0) d_logdet[s] = sLd;
}

// ---------------------------------------------------------------------------
// Kernel 4: blocked forward solve + maha + logp.
// Grid (8 btiles, 256 s), 256 threads. Btile = 128.
// Y_i = invL_ii (Diff_i - sum_{j<i} L_ij Y_j);  maha = sum Y^2  (Y overwrites Diff)
// dyn smem = (256*132 + 64*132 + 64*65 + 64*65 + 256 + 16*132)*4 = 211,712 B
// ---------------------------------------------------------------------------
__global__ __launch_bounds__(256) void maha_kernel(const float* __restrict__ x,
                                                   const float* __restrict__ mu,
                                                   float* __restrict__ out) {
    extern __shared__ float sm[];
    float* sDiff = sm;                    // [256][132]  (dim-major, batch pitch 132)
    float* sT    = sDiff + 256 * 132;     // [64][132]
    float* sL    = sT + 64 * 132;         // [64][65]
    float* sI    = sL + 64 * 65;          // [64][65]
    float* sMu   = sI + 64 * 65;          // [256]
    float* sMred = sMu + 256;             // [16][132]

    const int s = blockIdx.y;
    const int b0 = blockIdx.x * 128;
    const int tid = threadIdx.x, tx = tid & 15, ty = tid >> 4;

    sMu[tid] = mu[(size_t)s * DD + tid];
    __syncthreads();
    for (int idx = tid; idx < 128 * 256; idx += 256) {
        int b = idx >> 8, d = idx & 255;   // consecutive tid -> consecutive d (coalesced gmem)
        sDiff[d * 132 + b] = x[(size_t)(b0 + b) * DD + d] - sMu[d];
    }
    __syncthreads();

    const float* Lg = d_L + (size_t)s * DD * DD;
    const float* Ig = d_invDiag + (size_t)s * 4 * (NB * NB);

    float macc[8];
#pragma unroll
    for (int q = 0; q < 8; q++) macc[q] = 0.f;

    for (int i = 0; i < 4; i++) {
        // T := Diff_i
        float acc[4][8];
#pragma unroll
        for (int r = 0; r < 4; r++) {
            const float* p = &sDiff[(i * 64 + ty * 4 + r) * 132 + tx * 8];
            float4 v0 = *(const float4*)p;
            float4 v1 = *(const float4*)(p + 4);
            acc[r][0] = v0.x; acc[r][1] = v0.y; acc[r][2] = v0.z; acc[r][3] = v0.w;
            acc[r][4] = v1.x; acc[r][5] = v1.y; acc[r][6] = v1.z; acc[r][7] = v1.w;
        }
        // T -= L_ij * Y_j
        for (int j = 0; j < i; j++) {
            __syncthreads();
            for (int idx = tid; idx < NB * NB; idx += 256)
                sL[(idx >> 6) * 65 + (idx & 63)] = Lg[(size_t)(i * 64 + (idx >> 6)) * DD + j * 64 + (idx & 63)];
            __syncthreads();
#pragma unroll 4
            for (int c = 0; c < 64; c++) {
                float a0 = sL[(ty * 4 + 0) * 65 + c];
                float a1 = sL[(ty * 4 + 1) * 65 + c];
                float a2 = sL[(ty * 4 + 2) * 65 + c];
                float a3 = sL[(ty * 4 + 3) * 65 + c];
                const float* yp = &sDiff[(j * 64 + c) * 132 + tx * 8];
                float4 y0 = *(const float4*)yp;
                float4 y1 = *(const float4*)(yp + 4);
                float yv[8] = {y0.x, y0.y, y0.z, y0.w, y1.x, y1.y, y1.z, y1.w};
#pragma unroll
                for (int q = 0; q < 8; q++) {
                    acc[0][q] -= a0 * yv[q];
                    acc[1][q] -= a1 * yv[q];
                    acc[2][q] -= a2 * yv[q];
                    acc[3][q] -= a3 * yv[q];
                }
            }
        }
        __syncthreads();
        // store T, stage invL_ii
#pragma unroll
        for (int r = 0; r < 4; r++) {
            float* p = &sT[(ty * 4 + r) * 132 + tx * 8];
            *(float4*)p       = make_float4(acc[r][0], acc[r][1], acc[r][2], acc[r][3]);
            *(float4*)(p + 4) = make_float4(acc[r][4], acc[r][5], acc[r][6], acc[r][7]);
        }
        for (int idx = tid; idx < NB * NB; idx += 256)
            sI[(idx >> 6) * 65 + (idx & 63)] = Ig[(size_t)i * (NB * NB) + idx];
        __syncthreads();
        // Y_i = invL_ii * T
        float yy[4][8];
#pragma unroll
        for (int r = 0; r < 4; r++)
#pragma unroll
            for (int q = 0; q < 8; q++) yy[r][q] = 0.f;
#pragma unroll 4
        for (int c = 0; c < 64; c++) {
            float a0 = sI[(ty * 4 + 0) * 65 + c];
            float a1 = sI[(ty * 4 + 1) * 65 + c];
            float a2 = sI[(ty * 4 + 2) * 65 + c];
            float a3 = sI[(ty * 4 + 3) * 65 + c];
            const float* tp = &sT[c * 132 + tx * 8];
            float4 t0 = *(const float4*)tp;
            float4 t1 = *(const float4*)(tp + 4);
            float tv[8] = {t0.x, t0.y, t0.z, t0.w, t1.x, t1.y, t1.z, t1.w};
#pragma unroll
            for (int q = 0; q < 8; q++) {
                yy[0][q] += a0 * tv[q];
                yy[1][q] += a1 * tv[q];
                yy[2][q] += a2 * tv[q];
                yy[3][q] += a3 * tv[q];
            }
        }
        // Y overwrites Diff block i; accumulate squares
#pragma unroll
        for (int r = 0; r < 4; r++) {
            float* p = &sDiff[(i * 64 + ty * 4 + r) * 132 + tx * 8];
            *(float4*)p       = make_float4(yy[r][0], yy[r][1], yy[r][2], yy[r][3]);
            *(float4*)(p + 4) = make_float4(yy[r][4], yy[r][5], yy[r][6], yy[r][7]);
#pragma unroll
            for (int q = 0; q < 8; q++) macc[q] += yy[r][q] * yy[r][q];
        }
        __syncthreads();
    }
#pragma unroll
    for (int q = 0; q < 8; q++) sMred[ty * 132 + tx * 8 + q] = macc[q];
    __syncthreads();
    if (tid < 128) {
        float m = 0.f;
#pragma unroll
        for (int t = 0; t < 16; t++) m += sMred[t * 132 + tid];
        const float log2pi = 1.8378770664093453f;
        float lp = -0.5f * ((float)DD * log2pi + d_logdet[s] + m);
        out[(size_t)(b0 + tid) * SS + s] = lp;
    }
}

// ---------------------------------------------------------------------------
extern "C" void kernel_launch(void* const* d_in, const int* in_sizes, int n_in,
                              void* d_out, int out_size) {
    const float* x  = (const float*)d_in[0];   // (1024, 256)
    const float* mu = (const float*)d_in[1];   // (256, 1, 256)
    const float* sg = (const float*)d_in[2];   // (256, 1, 256, 256)
    float* out = (float*)d_out;                // (1024, 256)

    cudaFuncSetAttribute(chol_kernel, cudaFuncAttributeMaxDynamicSharedMemorySize, 83200);
    cudaFuncSetAttribute(maha_kernel, cudaFuncAttributeMaxDynamicSharedMemorySize, 211712);

    ridge_kernel<<<SS, 256>>>(sg);
    syrk_kernel<<<dim3(10, SS), 256>>>(sg);
    chol_kernel<<<SS, 256, 83200>>>();
    maha_kernel<<<dim3(8, SS), 256, 211712>>>(x, mu, out);
}

// round 9
// speedup vs baseline: 2.6208x; 2.6208x over previous
#include <cuda_runtime.h>
#include <cuda_bf16.h>
#include <math.h>
#include <stdint.h>

#define DD 256
#define SS 256
#define NB 64

// Scratch (device globals; no allocation allowed)
__device__ float d_L[(size_t)SS * DD * DD];            // 64 MB: Sigma -> L (lower valid)
__device__ float d_Linv[(size_t)SS * DD * DD];         // 64 MB: explicit L^-1 (block lower; (0,1),(2,3) zeroed)
__device__ float d_invDiag[(size_t)SS * 4 * NB * NB];  // inv of diag 64x64 blocks
__device__ float d_ridge[SS];
__device__ float d_logdet[SS];

// ======================= PTX helpers (sm_80-level only) =======================
__device__ __forceinline__ uint32_t smem_u32(const void* p) {
    uint32_t a;
    asm("{ .reg .u64 t; cvta.to.shared.u64 t, %1; cvt.u32.u64 %0, t; }" : "=r"(a) : "l"(p));
    return a;
}
__device__ __forceinline__ void ldsm_x4(uint32_t& r0, uint32_t& r1, uint32_t& r2, uint32_t& r3,
                                        uint32_t addr) {
    asm volatile("ldmatrix.sync.aligned.m8n8.x4.shared.b16 {%0,%1,%2,%3}, [%4];"
                 : "=r"(r0), "=r"(r1), "=r"(r2), "=r"(r3) : "r"(addr));
}
__device__ __forceinline__ void mma_bf16(float* d, const uint32_t* a, uint32_t b0, uint32_t b1) {
    asm volatile("mma.sync.aligned.m16n8k16.row.col.f32.bf16.bf16.f32 "
                 "{%0,%1,%2,%3}, {%4,%5,%6,%7}, {%8,%9}, {%0,%1,%2,%3};"
                 : "+f"(d[0]), "+f"(d[1]), "+f"(d[2]), "+f"(d[3])
                 : "r"(a[0]), "r"(a[1]), "r"(a[2]), "r"(a[3]), "r"(b0), "r"(b1));
}
__device__ __forceinline__ void cvt_split(float4 v, uint2& hi, uint2& lo) {
    __nv_bfloat16 h0 = __float2bfloat16(v.x), h1 = __float2bfloat16(v.y),
                  h2 = __float2bfloat16(v.z), h3 = __float2bfloat16(v.w);
    __nv_bfloat16 l0 = __float2bfloat16(v.x - __bfloat162float(h0));
    __nv_bfloat16 l1 = __float2bfloat16(v.y - __bfloat162float(h1));
    __nv_bfloat16 l2 = __float2bfloat16(v.z - __bfloat162float(h2));
    __nv_bfloat16 l3 = __float2bfloat16(v.w - __bfloat162float(h3));
    __nv_bfloat162 ph0 = __halves2bfloat162(h0, h1), ph1 = __halves2bfloat162(h2, h3);
    __nv_bfloat162 pl0 = __halves2bfloat162(l0, l1), pl1 = __halves2bfloat162(l2, l3);
    hi.x = *(uint32_t*)&ph0; hi.y = *(uint32_t*)&ph1;
    lo.x = *(uint32_t*)&pl0; lo.y = *(uint32_t*)&pl1;
}

// ---------------------------------------------------------------------------
// Kernel 1: ridge[s] = 0.01 * ||sp_s||_F^2 / D
// ---------------------------------------------------------------------------
__global__ __launch_bounds__(256) void ridge_kernel(const float* __restrict__ sp) {
    const int s = blockIdx.x;
    const float* A = sp + (size_t)s * DD * DD;
    float acc = 0.f;
    for (int i = threadIdx.x; i < DD * DD; i += 256) { float v = A[i]; acc += v * v; }
    __shared__ float red[256];
    red[threadIdx.x] = acc; __syncthreads();
    for (int o = 128; o > 0; o >>= 1) {
        if (threadIdx.x < o) red[threadIdx.x] += red[threadIdx.x + o];
        __syncthreads();
    }
    if (threadIdx.x == 0) d_ridge[s] = 0.01f * red[0] / (float)DD;
}

// ---------------------------------------------------------------------------
// Kernel 2: Sigma_s = sp^T sp + ridge*I, lower-triangle 64x64 tiles (10 tiles).
// ---------------------------------------------------------------------------
__global__ __launch_bounds__(256) void syrk_kernel(const float* __restrict__ sp) {
    const int t = blockIdx.x;
    const int ti = (int)((sqrtf(8.0f * t + 1.0f) - 1.0f) * 0.5f);
    const int tj = t - (ti * (ti + 1)) / 2;
    const int s = blockIdx.y;
    const float* A = sp + (size_t)s * DD * DD;
    float* C = d_L + (size_t)s * DD * DD;

    __shared__ float sA[16 * 65];
    __shared__ float sB[16 * 65];
    const int tid = threadIdx.x, tx = tid & 15, ty = tid >> 4;

    float acc[4][4];
#pragma unroll
    for (int r = 0; r < 4; r++)
#pragma unroll
        for (int c = 0; c < 4; c++) acc[r][c] = 0.f;

    for (int k0 = 0; k0 < DD; k0 += 16) {
        for (int idx = tid; idx < 1024; idx += 256) {
            int kk = idx >> 6, c = idx & 63;
            sA[kk * 65 + c] = A[(size_t)(k0 + kk) * DD + ti * NB + c];
            sB[kk * 65 + c] = A[(size_t)(k0 + kk) * DD + tj * NB + c];
        }
        __syncthreads();
#pragma unroll
        for (int kk = 0; kk < 16; kk++) {
            float a0 = sA[kk * 65 + ty * 4 + 0];
            float a1 = sA[kk * 65 + ty * 4 + 1];
            float a2 = sA[kk * 65 + ty * 4 + 2];
            float a3 = sA[kk * 65 + ty * 4 + 3];
            float b0 = sB[kk * 65 + tx * 4 + 0];
            float b1 = sB[kk * 65 + tx * 4 + 1];
            float b2 = sB[kk * 65 + tx * 4 + 2];
            float b3 = sB[kk * 65 + tx * 4 + 3];
            acc[0][0] += a0 * b0; acc[0][1] += a0 * b1; acc[0][2] += a0 * b2; acc[0][3] += a0 * b3;
            acc[1][0] += a1 * b0; acc[1][1] += a1 * b1; acc[1][2] += a1 * b2; acc[1][3] += a1 * b3;
            acc[2][0] += a2 * b0; acc[2][1] += a2 * b1; acc[2][2] += a2 * b2; acc[2][3] += a2 * b3;
            acc[3][0] += a3 * b0; acc[3][1] += a3 * b1; acc[3][2] += a3 * b2; acc[3][3] += a3 * b3;
        }
        __syncthreads();
    }
    if (ti == tj) {
        float ridge = d_ridge[s];
#pragma unroll
        for (int r = 0; r < 4; r++)
#pragma unroll
            for (int c = 0; c < 4; c++)
                if (ty * 4 + r == tx * 4 + c) acc[r][c] += ridge;
    }
#pragma unroll
    for (int r = 0; r < 4; r++) {
        float4 v = make_float4(acc[r][0], acc[r][1], acc[r][2], acc[r][3]);
        *(float4*)&C[(size_t)(ti * NB + ty * 4 + r) * DD + tj * NB + tx * 4] = v;
    }
}

// ---------------------------------------------------------------------------
// Kernel 3: per-s blocked Cholesky + diag-block inverses + logdet.
// ---------------------------------------------------------------------------
__global__ __launch_bounds__(256) void chol_kernel() {
    extern __shared__ float sm[];
    float* sP = sm;               // 256*65
    float* sI = sm + 256 * 65;    // 64*65
    __shared__ float sLd;
    const int s = blockIdx.x;
    const int tid = threadIdx.x;
    float* L = d_L + (size_t)s * DD * DD;
    if (tid == 0) sLd = 0.f;

    for (int p = 0; p < 4; p++) {
        const int r0 = p * NB;
        const int nrows = DD - r0;
        for (int idx = tid; idx < nrows * NB; idx += 256)
            sP[(idx >> 6) * 65 + (idx & 63)] = L[(size_t)(r0 + (idx >> 6)) * DD + r0 + (idx & 63)];
        __syncthreads();

        for (int j = 0; j < NB; j++) {
            float dj = sP[j * 65 + j];
            float rs = 1.0f / sqrtf(dj);
            if (tid == 0) sLd += logf(dj);
            for (int r = j + 1 + tid; r < nrows; r += 256) sP[r * 65 + j] *= rs;
            __syncthreads();
            int c = j + 1 + (tid & 63);
            if (c < NB) {
                float lc = sP[c * 65 + j];
                for (int r = j + 1 + (tid >> 6); r < nrows; r += 4)
                    sP[r * 65 + c] -= sP[r * 65 + j] * lc;
            }
            __syncthreads();
        }
        if (tid < NB) sP[tid * 65 + tid] = sqrtf(sP[tid * 65 + tid]);
        __syncthreads();

        for (int idx = tid; idx < nrows * NB; idx += 256)
            L[(size_t)(r0 + (idx >> 6)) * DD + r0 + (idx & 63)] = sP[(idx >> 6) * 65 + (idx & 63)];

        if (tid < NB) {
            int c = tid;
            for (int r = 0; r < NB; r++) {
                float v = (r == c) ? 1.f : 0.f;
                for (int k = c; k < r; k++) v -= sP[r * 65 + k] * sI[k * 65 + c];
                sI[r * 65 + c] = (r < c) ? 0.f : v / sP[r * 65 + r];
            }
        }
        __syncthreads();
        for (int idx = tid; idx < NB * NB; idx += 256)
            d_invDiag[((size_t)s * 4 + p) * (NB * NB) + idx] = sI[(idx >> 6) * 65 + (idx & 63)];

        const int nt = 3 - p;
        const int tx = tid & 15, ty = tid >> 4;
        for (int ti2 = 0; ti2 < nt; ti2++)
            for (int tj2 = 0; tj2 < nt; tj2++) {
                int lr = NB + ti2 * NB + ty * 4;
                int lc = NB + tj2 * NB + tx * 4;
                float accm[4][4];
#pragma unroll
                for (int r = 0; r < 4; r++) {
                    float4 v = *(float4*)&L[(size_t)(r0 + lr + r) * DD + r0 + lc];
                    accm[r][0] = v.x; accm[r][1] = v.y; accm[r][2] = v.z; accm[r][3] = v.w;
                }
#pragma unroll 4
                for (int k = 0; k < NB; k++) {
                    float a0 = sP[(lr + 0) * 65 + k];
                    float a1 = sP[(lr + 1) * 65 + k];
                    float a2 = sP[(lr + 2) * 65 + k];
                    float a3 = sP[(lr + 3) * 65 + k];
                    float b0 = sP[(lc + 0) * 65 + k];
                    float b1 = sP[(lc + 1) * 65 + k];
                    float b2 = sP[(lc + 2) * 65 + k];
                    float b3 = sP[(lc + 3) * 65 + k];
                    accm[0][0] -= a0 * b0; accm[0][1] -= a0 * b1; accm[0][2] -= a0 * b2; accm[0][3] -= a0 * b3;
                    accm[1][0] -= a1 * b0; accm[1][1] -= a1 * b1; accm[1][2] -= a1 * b2; accm[1][3] -= a1 * b3;
                    accm[2][0] -= a2 * b0; accm[2][1] -= a2 * b1; accm[2][2] -= a2 * b2; accm[2][3] -= a2 * b3;
                    accm[3][0] -= a3 * b0; accm[3][1] -= a3 * b1; accm[3][2] -= a3 * b2; accm[3][3] -= a3 * b3;
                }
#pragma unroll
                for (int r = 0; r < 4; r++) {
                    float4 v = make_float4(accm[r][0], accm[r][1], accm[r][2], accm[r][3]);
                    *(float4*)&L[(size_t)(r0 + lr + r) * DD + r0 + lc] = v;
                }
            }
        __syncthreads();
    }
    if (tid == 0) d_logdet[s] = sLd;
}

// ---------------------------------------------------------------------------
// Kernel 3b: explicit Linv (block lower-triangular inverse). One CTA per s.
// Also zeroes blocks (0,1) and (2,3) (read by the GEMM halves).
// dyn smem = 3 * 64*68 * 4 = 52224 B
// ---------------------------------------------------------------------------
__global__ __launch_bounds__(256) void linv_kernel() {
    extern __shared__ float sm[];
    float* sA = sm;                 // [64][68]
    float* sB = sm + 64 * 68;       // [64][68]
    float* sM = sB + 64 * 68;       // [64][68]
    const int s = blockIdx.x;
    const int tid = threadIdx.x, tx = tid & 15, ty = tid >> 4;
    const float* L = d_L + (size_t)s * DD * DD;
    const float* ID = d_invDiag + (size_t)s * 4 * (NB * NB);
    float* V = d_Linv + (size_t)s * DD * DD;

    for (int p = 0; p < 4; p++)
        for (int idx = tid; idx < NB * NB; idx += 256)
            V[(size_t)(p * 64 + (idx >> 6)) * DD + p * 64 + (idx & 63)] = ID[p * NB * NB + idx];
    for (int idx = tid; idx < NB * NB; idx += 256) {
        V[(size_t)(idx >> 6) * DD + 64 + (idx & 63)] = 0.f;
        V[(size_t)(128 + (idx >> 6)) * DD + 192 + (idx & 63)] = 0.f;
    }
    __syncthreads();

    for (int i = 1; i < 4; i++) {
        for (int j = 0; j < i; j++) {
            float acc[4][4];
#pragma unroll
            for (int r = 0; r < 4; r++)
#pragma unroll
                for (int c = 0; c < 4; c++) acc[r][c] = 0.f;
            for (int k = j; k < i; k++) {
                __syncthreads();
                for (int idx = tid; idx < NB * NB; idx += 256) {
                    int rr = idx >> 6, cc = idx & 63;
                    sA[rr * 68 + cc] = L[(size_t)(i * 64 + rr) * DD + k * 64 + cc];
                    sB[rr * 68 + cc] = (k == j) ? ID[j * NB * NB + idx]
                                                : V[(size_t)(k * 64 + rr) * DD + j * 64 + cc];
                }
                __syncthreads();
#pragma unroll 4
                for (int kk = 0; kk < 64; kk++) {
                    float a0 = sA[(ty * 4 + 0) * 68 + kk];
                    float a1 = sA[(ty * 4 + 1) * 68 + kk];
                    float a2 = sA[(ty * 4 + 2) * 68 + kk];
                    float a3 = sA[(ty * 4 + 3) * 68 + kk];
                    float4 b = *(const float4*)&sB[kk * 68 + tx * 4];
                    acc[0][0] += a0 * b.x; acc[0][1] += a0 * b.y; acc[0][2] += a0 * b.z; acc[0][3] += a0 * b.w;
                    acc[1][0] += a1 * b.x; acc[1][1] += a1 * b.y; acc[1][2] += a1 * b.z; acc[1][3] += a1 * b.w;
                    acc[2][0] += a2 * b.x; acc[2][1] += a2 * b.y; acc[2][2] += a2 * b.z; acc[2][3] += a2 * b.w;
                    acc[3][0] += a3 * b.x; acc[3][1] += a3 * b.y; acc[3][2] += a3 * b.z; acc[3][3] += a3 * b.w;
                }
            }
            __syncthreads();
#pragma unroll
            for (int r = 0; r < 4; r++)
#pragma unroll
                for (int c = 0; c < 4; c++) sM[(ty * 4 + r) * 68 + tx * 4 + c] = acc[r][c];
            for (int idx = tid; idx < NB * NB; idx += 256)
                sA[(idx >> 6) * 68 + (idx & 63)] = ID[i * NB * NB + idx];
            __syncthreads();
            float o[4][4];
#pragma unroll
            for (int r = 0; r < 4; r++)
#pragma unroll
                for (int c = 0; c < 4; c++) o[r][c] = 0.f;
#pragma unroll 4
            for (int kk = 0; kk < 64; kk++) {
                float a0 = sA[(ty * 4 + 0) * 68 + kk];
                float a1 = sA[(ty * 4 + 1) * 68 + kk];
                float a2 = sA[(ty * 4 + 2) * 68 + kk];
                float a3 = sA[(ty * 4 + 3) * 68 + kk];
                float4 b = *(const float4*)&sM[kk * 68 + tx * 4];
                o[0][0] -= a0 * b.x; o[0][1] -= a0 * b.y; o[0][2] -= a0 * b.z; o[0][3] -= a0 * b.w;
                o[1][0] -= a1 * b.x; o[1][1] -= a1 * b.y; o[1][2] -= a1 * b.z; o[1][3] -= a1 * b.w;
                o[2][0] -= a2 * b.x; o[2][1] -= a2 * b.y; o[2][2] -= a2 * b.z; o[2][3] -= a2 * b.w;
                o[3][0] -= a3 * b.x; o[3][1] -= a3 * b.y; o[3][2] -= a3 * b.z; o[3][3] -= a3 * b.w;
            }
#pragma unroll
            for (int r = 0; r < 4; r++) {
                float4 v = make_float4(o[r][0], o[r][1], o[r][2], o[r][3]);
                *(float4*)&V[(size_t)(i * 64 + ty * 4 + r) * DD + j * 64 + tx * 4] = v;
            }
            __syncthreads();
        }
    }
}

// ---------------------------------------------------------------------------
// Kernel 4a: out[b][s] = -0.5*(D*log2pi + logdet[s])   (base for atomic maha)
// ---------------------------------------------------------------------------
__global__ __launch_bounds__(256) void init_out_kernel(float* __restrict__ out) {
    const float log2pi = 1.8378770664093453f;
    int b = blockIdx.x, s = threadIdx.x;
    out[(size_t)b * SS + s] = -0.5f * ((float)DD * log2pi + d_logdet[s]);
}

// ---------------------------------------------------------------------------
// Kernel 4b: mma.sync bf16-split GEMM  Z = Linv_half * Diff^T, maha += colsum(Z^2)
// grid (btile=8, half=2, s=256), 256 thr = 8 warps, warp tile 32(m) x 64(n).
// K = 128 (h=0) or 256 (h=1), chunked by 64; 3 split MMAs per (m16,n8,k16).
// smem: 4 bf16 planes [128][72] = 73728 B (Ahi, Alo, Bhi, Blo).
// ---------------------------------------------------------------------------
#define LDA 72
__global__ __launch_bounds__(256) void mahaZ_kernel(const float* __restrict__ x,
                                                    const float* __restrict__ mu,
                                                    float* __restrict__ out) {
    extern __shared__ __nv_bfloat16 smh[];
    const uint32_t sbase = smem_u32(smh);
    const int tid = threadIdx.x, wid = tid >> 5, lane = tid & 31;
    const int wm = wid & 3, wn = wid >> 2;
    const int b0 = blockIdx.x * 128, h = blockIdx.y, s = blockIdx.z;
    const int nchunks = 2 * (h + 1);

    // plane element offsets within smem (bf16 elems)
    const uint32_t AHI = 0, ALO = 128 * LDA, BHI = 2 * 128 * LDA, BLO = 3 * 128 * LDA;

    const float* Asrc = d_Linv + ((size_t)s * DD + h * 128) * DD;
    const float* Bsrc = x + (size_t)b0 * DD;
    const float* msrc = mu + (size_t)s * DD;

    float acc[2][8][4];
#pragma unroll
    for (int i = 0; i < 2; i++)
#pragma unroll
        for (int j = 0; j < 8; j++)
#pragma unroll
            for (int r = 0; r < 4; r++) acc[i][j][r] = 0.f;

    // ldmatrix source addresses (byte)
    const uint32_t aRow = wm * 32 + (lane & 15);
    const uint32_t aColOff = ((lane >> 4) << 3);
    const uint32_t bRow = wn * 64 + (lane & 7) + ((lane >> 4) << 3);
    const uint32_t bColOff = (((lane >> 3) & 1) << 3);

    for (int c = 0; c < nchunks; c++) {
        const int k0 = c * 64;
        // ---- stage chunk: fp32 -> bf16 hi/lo planes ----
        for (int idx = tid; idx < 2048; idx += 256) {
            int row = idx >> 4, q = idx & 15;       // q*4 = k offset in chunk
            uint2 hi, lo;
            {   // A (Linv)
                float4 v = *(const float4*)(Asrc + (size_t)row * DD + k0 + q * 4);
                cvt_split(v, hi, lo);
                *(uint2*)(smh + AHI + row * LDA + q * 4) = hi;
                *(uint2*)(smh + ALO + row * LDA + q * 4) = lo;
            }
            {   // B (x - mu)
                float4 v = *(const float4*)(Bsrc + (size_t)row * DD + k0 + q * 4);
                float4 m4 = *(const float4*)(msrc + k0 + q * 4);
                v.x -= m4.x; v.y -= m4.y; v.z -= m4.z; v.w -= m4.w;
                cvt_split(v, hi, lo);
                *(uint2*)(smh + BHI + row * LDA + q * 4) = hi;
                *(uint2*)(smh + BLO + row * LDA + q * 4) = lo;
            }
        }
        __syncthreads();

        // ---- compute: 4 k16 steps ----
#pragma unroll
        for (int ks = 0; ks < 4; ks++) {
            const uint32_t kc = ks * 16;
            uint32_t ahi[2][4], alo[2][4];
#pragma unroll
            for (int i = 0; i < 2; i++) {
                uint32_t ra = (aRow + i * 16) * LDA + kc + aColOff;
                ldsm_x4(ahi[i][0], ahi[i][1], ahi[i][2], ahi[i][3], sbase + (AHI + ra) * 2);
                ldsm_x4(alo[i][0], alo[i][1], alo[i][2], alo[i][3], sbase + (ALO + ra) * 2);
            }
#pragma unroll
            for (int p = 0; p < 4; p++) {
                uint32_t bhi[4], blo[4];
                uint32_t rb = (bRow + p * 16) * LDA + kc + bColOff;
                ldsm_x4(bhi[0], bhi[1], bhi[2], bhi[3], sbase + (BHI + rb) * 2);
                ldsm_x4(blo[0], blo[1], blo[2], blo[3], sbase + (BLO + rb) * 2);
#pragma unroll
                for (int i = 0; i < 2; i++) {
                    mma_bf16(acc[i][2 * p + 0], ahi[i], bhi[0], bhi[1]);
                    mma_bf16(acc[i][2 * p + 1], ahi[i], bhi[2], bhi[3]);
                    mma_bf16(acc[i][2 * p + 0], ahi[i], blo[0], blo[1]);
                    mma_bf16(acc[i][2 * p + 1], ahi[i], blo[2], blo[3]);
                    mma_bf16(acc[i][2 * p + 0], alo[i], bhi[0], bhi[1]);
                    mma_bf16(acc[i][2 * p + 1], alo[i], bhi[2], bhi[3]);
                }
            }
        }
        __syncthreads();
    }

    // ---- epilogue: column sums of Z^2 ----
    // thread's columns (within warp's n64): j*8 + 2*(lane%4) + {0,1}; rows: lane/4 (+8), both m-tiles
    float* sRed = (float*)smh;   // [8][64]
    float cs0[8], cs1[8];
#pragma unroll
    for (int j = 0; j < 8; j++) {
        float s0 = 0.f, s1 = 0.f;
#pragma unroll
        for (int i = 0; i < 2; i++) {
            s0 += acc[i][j][0] * acc[i][j][0] + acc[i][j][2] * acc[i][j][2];
            s1 += acc[i][j][1] * acc[i][j][1] + acc[i][j][3] * acc[i][j][3];
        }
#pragma unroll
        for (int o = 4; o <= 16; o <<= 1) {
            s0 += __shfl_xor_sync(0xFFFFFFFF, s0, o);
            s1 += __shfl_xor_sync(0xFFFFFFFF, s1, o);
        }
        cs0[j] = s0; cs1[j] = s1;
    }
    if (lane < 4) {
#pragma unroll
        for (int j = 0; j < 8; j++) {
            sRed[wid * 64 + j * 8 + 2 * lane + 0] = cs0[j];
            sRed[wid * 64 + j * 8 + 2 * lane + 1] = cs1[j];
        }
    }
    __syncthreads();
    if (tid < 128) {
        int nn = tid & 63, g = (tid >> 6) * 4;   // warps g..g+3 cover this n-half
        float m = sRed[(g + 0) * 64 + nn] + sRed[(g + 1) * 64 + nn]
                + sRed[(g + 2) * 64 + nn] + sRed[(g + 3) * 64 + nn];
        atomicAdd(&out[(size_t)(b0 + tid) * SS + s], -0.5f * m);
    }
}

// ---------------------------------------------------------------------------
extern "C" void kernel_launch(void* const* d_in, const int* in_sizes, int n_in,
                              void* d_out, int out_size) {
    const float* x  = (const float*)d_in[0];   // (1024, 256)
    const float* mu = (const float*)d_in[1];   // (256, 1, 256)
    const float* sg = (const float*)d_in[2];   // (256, 1, 256, 256)
    float* out = (float*)d_out;                // (1024, 256)

    cudaFuncSetAttribute(chol_kernel,  cudaFuncAttributeMaxDynamicSharedMemorySize, 83200);
    cudaFuncSetAttribute(linv_kernel,  cudaFuncAttributeMaxDynamicSharedMemorySize, 52224);
    cudaFuncSetAttribute(mahaZ_kernel, cudaFuncAttributeMaxDynamicSharedMemorySize, 73728);

    ridge_kernel<<<SS, 256>>>(sg);
    syrk_kernel<<<dim3(10, SS), 256>>>(sg);
    chol_kernel<<<SS, 256, 83200>>>();
    linv_kernel<<<SS, 256, 52224>>>();
    init_out_kernel<<<1024, 256>>>(out);
    mahaZ_kernel<<<dim3(8, 2, SS), 256, 73728>>>(x, mu, out);
}

// round 11
// speedup vs baseline: 2.8694x; 1.0949x over previous
#include <cuda_runtime.h>
#include <cuda_bf16.h>
#include <math.h>
#include <stdint.h>

#define DD 256
#define SS 256
#define NB 64

// Scratch (device globals; no allocation allowed)
__device__ float d_L[(size_t)SS * DD * DD];            // 64 MB: Sigma -> L (lower valid)
__device__ float d_Linv[(size_t)SS * DD * DD];         // 64 MB: explicit L^-1 (block lower; (0,1),(2,3) zeroed)
__device__ float d_invDiag[(size_t)SS * 4 * NB * NB];  // inv of diag 64x64 blocks
__device__ float d_ridge[SS];
__device__ float d_logdet[SS];

// ======================= PTX helpers (sm_80-level only) =======================
__device__ __forceinline__ uint32_t smem_u32(const void* p) {
    uint32_t a;
    asm("{ .reg .u64 t; cvta.to.shared.u64 t, %1; cvt.u32.u64 %0, t; }" : "=r"(a) : "l"(p));
    return a;
}
__device__ __forceinline__ void ldsm_x4(uint32_t& r0, uint32_t& r1, uint32_t& r2, uint32_t& r3,
                                        uint32_t addr) {
    asm volatile("ldmatrix.sync.aligned.m8n8.x4.shared.b16 {%0,%1,%2,%3}, [%4];"
                 : "=r"(r0), "=r"(r1), "=r"(r2), "=r"(r3) : "r"(addr));
}
__device__ __forceinline__ void ldsm_x4t(uint32_t& r0, uint32_t& r1, uint32_t& r2, uint32_t& r3,
                                         uint32_t addr) {
    asm volatile("ldmatrix.sync.aligned.m8n8.x4.trans.shared.b16 {%0,%1,%2,%3}, [%4];"
                 : "=r"(r0), "=r"(r1), "=r"(r2), "=r"(r3) : "r"(addr));
}
__device__ __forceinline__ void mma_bf16(float* d, const uint32_t* a, uint32_t b0, uint32_t b1) {
    asm volatile("mma.sync.aligned.m16n8k16.row.col.f32.bf16.bf16.f32 "
                 "{%0,%1,%2,%3}, {%4,%5,%6,%7}, {%8,%9}, {%0,%1,%2,%3};"
                 : "+f"(d[0]), "+f"(d[1]), "+f"(d[2]), "+f"(d[3])
                 : "r"(a[0]), "r"(a[1]), "r"(a[2]), "r"(a[3]), "r"(b0), "r"(b1));
}
__device__ __forceinline__ void cvt_split(float4 v, uint2& hi, uint2& lo) {
    __nv_bfloat16 h0 = __float2bfloat16(v.x), h1 = __float2bfloat16(v.y),
                  h2 = __float2bfloat16(v.z), h3 = __float2bfloat16(v.w);
    __nv_bfloat16 l0 = __float2bfloat16(v.x - __bfloat162float(h0));
    __nv_bfloat16 l1 = __float2bfloat16(v.y - __bfloat162float(h1));
    __nv_bfloat16 l2 = __float2bfloat16(v.z - __bfloat162float(h2));
    __nv_bfloat16 l3 = __float2bfloat16(v.w - __bfloat162float(h3));
    __nv_bfloat162 ph0 = __halves2bfloat162(h0, h1), ph1 = __halves2bfloat162(h2, h3);
    __nv_bfloat162 pl0 = __halves2bfloat162(l0, l1), pl1 = __halves2bfloat162(l2, l3);
    hi.x = *(uint32_t*)&ph0; hi.y = *(uint32_t*)&ph1;
    lo.x = *(uint32_t*)&pl0; lo.y = *(uint32_t*)&pl1;
}

// ---------------------------------------------------------------------------
// Kernel 1: ridge[s] = 0.01 * ||sp_s||_F^2 / D
// ---------------------------------------------------------------------------
__global__ __launch_bounds__(256) void ridge_kernel(const float* __restrict__ sp) {
    const int s = blockIdx.x;
    const float* A = sp + (size_t)s * DD * DD;
    float acc = 0.f;
    for (int i = threadIdx.x; i < DD * DD; i += 256) { float v = A[i]; acc += v * v; }
    __shared__ float red[256];
    red[threadIdx.x] = acc; __syncthreads();
    for (int o = 128; o > 0; o >>= 1) {
        if (threadIdx.x < o) red[threadIdx.x] += red[threadIdx.x + o];
        __syncthreads();
    }
    if (threadIdx.x == 0) d_ridge[s] = 0.01f * red[0] / (float)DD;
}

// ---------------------------------------------------------------------------
// Kernel 2: Sigma_s = sp^T sp + ridge*I via mma.sync bf16-split.
// grid (3 tiles of 128x128: (0,0),(1,0),(1,1), s). Stage sp chunk [64 k][256 d]
// bf16 hi/lo (native layout, coalesced); A and B fragments via ldmatrix.trans.
// smem = 2 * 64*264 * 2B = 67584 B.
// ---------------------------------------------------------------------------
#define SLDK 264
__global__ __launch_bounds__(256) void syrk_kernel(const float* __restrict__ sp) {
    extern __shared__ __nv_bfloat16 smh[];
    const uint32_t sbase = smem_u32(smh);
    const uint32_t LO = 64 * SLDK;   // elem offset of lo plane
    const int t = blockIdx.x;
    const int ti = (t + 1) >> 1, tj = t >> 1;   // (0,0),(1,0),(1,1)
    const int s = blockIdx.y;
    const float* A = sp + (size_t)s * DD * DD;
    float* C = d_L + (size_t)s * DD * DD;

    const int tid = threadIdx.x, wid = tid >> 5, lane = tid & 31;
    const int wm = wid & 3, wn = wid >> 2;
    const int m0 = ti * 128 + wm * 32, n0 = tj * 128 + wn * 64;

    const int lt = lane >> 3, lr = lane & 7;
    const uint32_t aK = lr + 8 * (lt >> 1), aM = 8 * (lt & 1);   // A frag lane map
    const uint32_t bK = lr + 8 * (lt & 1),  bN = 8 * (lt >> 1);  // B frag lane map

    float acc[2][8][4];
#pragma unroll
    for (int i = 0; i < 2; i++)
#pragma unroll
        for (int j = 0; j < 8; j++)
#pragma unroll
            for (int r = 0; r < 4; r++) acc[i][j][r] = 0.f;

    for (int k0 = 0; k0 < DD; k0 += 64) {
        // stage [64 k][256 d] hi/lo
        for (int idx = tid; idx < 4096; idx += 256) {
            int k = idx >> 6, dq = (idx & 63) << 2;
            float4 v = *(const float4*)(A + (size_t)(k0 + k) * DD + dq);
            uint2 hi, lo; cvt_split(v, hi, lo);
            *(uint2*)(smh + k * SLDK + dq) = hi;
            *(uint2*)(smh + LO + k * SLDK + dq) = lo;
        }
        __syncthreads();
#pragma unroll
        for (int ks = 0; ks < 4; ks++) {
            const uint32_t kc = ks * 16;
            uint32_t ahi[2][4], alo[2][4];
#pragma unroll
            for (int i = 0; i < 2; i++) {
                uint32_t ra = (kc + aK) * SLDK + m0 + i * 16 + aM;
                ldsm_x4t(ahi[i][0], ahi[i][1], ahi[i][2], ahi[i][3], sbase + ra * 2);
                ldsm_x4t(alo[i][0], alo[i][1], alo[i][2], alo[i][3], sbase + (LO + ra) * 2);
            }
#pragma unroll
            for (int p = 0; p < 4; p++) {
                uint32_t bhi[4], blo[4];
                uint32_t rb = (kc + bK) * SLDK + n0 + p * 16 + bN;
                ldsm_x4t(bhi[0], bhi[1], bhi[2], bhi[3], sbase + rb * 2);
                ldsm_x4t(blo[0], blo[1], blo[2], blo[3], sbase + (LO + rb) * 2);
#pragma unroll
                for (int i = 0; i < 2; i++) {
                    mma_bf16(acc[i][2 * p + 0], ahi[i], bhi[0], bhi[1]);
                    mma_bf16(acc[i][2 * p + 1], ahi[i], bhi[2], bhi[3]);
                    mma_bf16(acc[i][2 * p + 0], ahi[i], blo[0], blo[1]);
                    mma_bf16(acc[i][2 * p + 1], ahi[i], blo[2], blo[3]);
                    mma_bf16(acc[i][2 * p + 0], alo[i], bhi[0], bhi[1]);
                    mma_bf16(acc[i][2 * p + 1], alo[i], bhi[2], bhi[3]);
                }
            }
        }
        __syncthreads();
    }

    // epilogue: += ridge on exact diagonal, write fp32 C
    const float ridge = d_ridge[s];
    const int crow = lane >> 2, ccol = 2 * (lane & 3);
#pragma unroll
    for (int i = 0; i < 2; i++)
#pragma unroll
        for (int j = 0; j < 8; j++) {
            int row = m0 + i * 16 + crow;
            int col = n0 + j * 8 + ccol;
            float c0 = acc[i][j][0], c1 = acc[i][j][1], c2 = acc[i][j][2], c3 = acc[i][j][3];
            if (row == col) c0 += ridge;
            if (row == col + 1) c1 += ridge;
            if (row + 8 == col) c2 += ridge;
            if (row + 8 == col + 1) c3 += ridge;
            *(float2*)&C[(size_t)row * DD + col] = make_float2(c0, c1);
            *(float2*)&C[(size_t)(row + 8) * DD + col] = make_float2(c2, c3);
        }
}

// ---------------------------------------------------------------------------
// Kernel 3: per-s blocked Cholesky + diag-block inverses + logdet.
// ---------------------------------------------------------------------------
__global__ __launch_bounds__(256) void chol_kernel() {
    extern __shared__ float sm[];
    float* sP = sm;               // 256*65
    float* sI = sm + 256 * 65;    // 64*65
    __shared__ float sLd;
    const int s = blockIdx.x;
    const int tid = threadIdx.x;
    float* L = d_L + (size_t)s * DD * DD;
    if (tid == 0) sLd = 0.f;

    for (int p = 0; p < 4; p++) {
        const int r0 = p * NB;
        const int nrows = DD - r0;
        for (int idx = tid; idx < nrows * NB; idx += 256)
            sP[(idx >> 6) * 65 + (idx & 63)] = L[(size_t)(r0 + (idx >> 6)) * DD + r0 + (idx & 63)];
        __syncthreads();

        for (int j = 0; j < NB; j++) {
            float dj = sP[j * 65 + j];
            float rs = 1.0f / sqrtf(dj);
            if (tid == 0) sLd += logf(dj);
            for (int r = j + 1 + tid; r < nrows; r += 256) sP[r * 65 + j] *= rs;
            __syncthreads();
            int c = j + 1 + (tid & 63);
            if (c < NB) {
                float lc = sP[c * 65 + j];
                for (int r = j + 1 + (tid >> 6); r < nrows; r += 4)
                    sP[r * 65 + c] -= sP[r * 65 + j] * lc;
            }
            __syncthreads();
        }
        if (tid < NB) sP[tid * 65 + tid] = sqrtf(sP[tid * 65 + tid]);
        __syncthreads();

        for (int idx = tid; idx < nrows * NB; idx += 256)
            L[(size_t)(r0 + (idx >> 6)) * DD + r0 + (idx & 63)] = sP[(idx >> 6) * 65 + (idx & 63)];

        if (tid < NB) {
            int c = tid;
            for (int r = 0; r < NB; r++) {
                float v = (r == c) ? 1.f : 0.f;
                for (int k = c; k < r; k++) v -= sP[r * 65 + k] * sI[k * 65 + c];
                sI[r * 65 + c] = (r < c) ? 0.f : v / sP[r * 65 + r];
            }
        }
        __syncthreads();
        for (int idx = tid; idx < NB * NB; idx += 256)
            d_invDiag[((size_t)s * 4 + p) * (NB * NB) + idx] = sI[(idx >> 6) * 65 + (idx & 63)];

        const int nt = 3 - p;
        const int tx = tid & 15, ty = tid >> 4;
        for (int ti2 = 0; ti2 < nt; ti2++)
            for (int tj2 = 0; tj2 < nt; tj2++) {
                int lr = NB + ti2 * NB + ty * 4;
                int lc = NB + tj2 * NB + tx * 4;
                float accm[4][4];
#pragma unroll
                for (int r = 0; r < 4; r++) {
                    float4 v = *(float4*)&L[(size_t)(r0 + lr + r) * DD + r0 + lc];
                    accm[r][0] = v.x; accm[r][1] = v.y; accm[r][2] = v.z; accm[r][3] = v.w;
                }
#pragma unroll 4
                for (int k = 0; k < NB; k++) {
                    float a0 = sP[(lr + 0) * 65 + k];
                    float a1 = sP[(lr + 1) * 65 + k];
                    float a2 = sP[(lr + 2) * 65 + k];
                    float a3 = sP[(lr + 3) * 65 + k];
                    float b0 = sP[(lc + 0) * 65 + k];
                    float b1 = sP[(lc + 1) * 65 + k];
                    float b2 = sP[(lc + 2) * 65 + k];
                    float b3 = sP[(lc + 3) * 65 + k];
                    accm[0][0] -= a0 * b0; accm[0][1] -= a0 * b1; accm[0][2] -= a0 * b2; accm[0][3] -= a0 * b3;
                    accm[1][0] -= a1 * b0; accm[1][1] -= a1 * b1; accm[1][2] -= a1 * b2; accm[1][3] -= a1 * b3;
                    accm[2][0] -= a2 * b0; accm[2][1] -= a2 * b1; accm[2][2] -= a2 * b2; accm[2][3] -= a2 * b3;
                    accm[3][0] -= a3 * b0; accm[3][1] -= a3 * b1; accm[3][2] -= a3 * b2; accm[3][3] -= a3 * b3;
                }
#pragma unroll
                for (int r = 0; r < 4; r++) {
                    float4 v = make_float4(accm[r][0], accm[r][1], accm[r][2], accm[r][3]);
                    *(float4*)&L[(size_t)(r0 + lr + r) * DD + r0 + lc] = v;
                }
            }
        __syncthreads();
    }
    if (tid == 0) d_logdet[s] = sLd;
}

// ---------------------------------------------------------------------------
// Kernel 3b: explicit Linv, COLUMN-PARALLEL. grid (s, j=0..2), chain over i
// stays in smem. CTA j also writes diag block j (j==2 also block 3) and the
// zero blocks ((0,1) by j==0, (2,3) by j==1).
// dyn smem = 5 * 64*68 * 4 = 87040 B
// ---------------------------------------------------------------------------
__global__ __launch_bounds__(256) void linv_kernel() {
    extern __shared__ float sm[];
    float* sV = sm;                     // [3][64*68]  column chain blocks (k = j..2)
    float* sL = sm + 3 * 64 * 68;       // [64][68]
    float* sM = sL + 64 * 68;           // [64][68]
    const int s = blockIdx.x, j = blockIdx.y;
    const int tid = threadIdx.x, tx = tid & 15, ty = tid >> 4;
    const float* L = d_L + (size_t)s * DD * DD;
    const float* ID = d_invDiag + (size_t)s * 4 * (NB * NB);
    float* V = d_Linv + (size_t)s * DD * DD;

    // seed chain with invD_j; write diag block j; extra duties
    for (int idx = tid; idx < NB * NB; idx += 256) {
        int rr = idx >> 6, cc = idx & 63;
        float v = ID[j * NB * NB + idx];
        sV[rr * 68 + cc] = v;
        V[(size_t)(j * 64 + rr) * DD + j * 64 + cc] = v;
        if (j == 0) V[(size_t)rr * DD + 64 + cc] = 0.f;
        if (j == 1) V[(size_t)(128 + rr) * DD + 192 + cc] = 0.f;
        if (j == 2) V[(size_t)(192 + rr) * DD + 192 + cc] = ID[3 * NB * NB + idx];
    }
    __syncthreads();

    for (int i = j + 1; i < 4; i++) {
        float acc[4][4];
#pragma unroll
        for (int r = 0; r < 4; r++)
#pragma unroll
            for (int c = 0; c < 4; c++) acc[r][c] = 0.f;
        for (int k = j; k < i; k++) {
            for (int idx = tid; idx < NB * NB; idx += 256)
                sL[(idx >> 6) * 68 + (idx & 63)] = L[(size_t)(i * 64 + (idx >> 6)) * DD + k * 64 + (idx & 63)];
            __syncthreads();
            const float* Vb = sV + (k - j) * 64 * 68;
#pragma unroll 4
            for (int kk = 0; kk < 64; kk++) {
                float a0 = sL[(ty * 4 + 0) * 68 + kk];
                float a1 = sL[(ty * 4 + 1) * 68 + kk];
                float a2 = sL[(ty * 4 + 2) * 68 + kk];
                float a3 = sL[(ty * 4 + 3) * 68 + kk];
                float4 b = *(const float4*)&Vb[kk * 68 + tx * 4];
                acc[0][0] += a0 * b.x; acc[0][1] += a0 * b.y; acc[0][2] += a0 * b.z; acc[0][3] += a0 * b.w;
                acc[1][0] += a1 * b.x; acc[1][1] += a1 * b.y; acc[1][2] += a1 * b.z; acc[1][3] += a1 * b.w;
                acc[2][0] += a2 * b.x; acc[2][1] += a2 * b.y; acc[2][2] += a2 * b.z; acc[2][3] += a2 * b.w;
                acc[3][0] += a3 * b.x; acc[3][1] += a3 * b.y; acc[3][2] += a3 * b.z; acc[3][3] += a3 * b.w;
            }
            __syncthreads();   // before sL overwritten next k
        }
        // sM = acc; sL = invD_i
#pragma unroll
        for (int r = 0; r < 4; r++)
#pragma unroll
            for (int c = 0; c < 4; c++) sM[(ty * 4 + r) * 68 + tx * 4 + c] = acc[r][c];
        for (int idx = tid; idx < NB * NB; idx += 256)
            sL[(idx >> 6) * 68 + (idx & 63)] = ID[i * NB * NB + idx];
        __syncthreads();
        float o[4][4];
#pragma unroll
        for (int r = 0; r < 4; r++)
#pragma unroll
            for (int c = 0; c < 4; c++) o[r][c] = 0.f;
#pragma unroll 4
        for (int kk = 0; kk < 64; kk++) {
            float a0 = sL[(ty * 4 + 0) * 68 + kk];
            float a1 = sL[(ty * 4 + 1) * 68 + kk];
            float a2 = sL[(ty * 4 + 2) * 68 + kk];
            float a3 = sL[(ty * 4 + 3) * 68 + kk];
            float4 b = *(const float4*)&sM[kk * 68 + tx * 4];
            o[0][0] -= a0 * b.x; o[0][1] -= a0 * b.y; o[0][2] -= a0 * b.z; o[0][3] -= a0 * b.w;
            o[1][0] -= a1 * b.x; o[1][1] -= a1 * b.y; o[1][2] -= a1 * b.z; o[1][3] -= a1 * b.w;
            o[2][0] -= a2 * b.x; o[2][1] -= a2 * b.y; o[2][2] -= a2 * b.z; o[2][3] -= a2 * b.w;
            o[3][0] -= a3 * b.x; o[3][1] -= a3 * b.y; o[3][2] -= a3 * b.z; o[3][3] -= a3 * b.w;
        }
        __syncthreads();   // sM reads done before (potential) reuse; also orders sV write below
#pragma unroll
        for (int r = 0; r < 4; r++) {
            float4 v = make_float4(o[r][0], o[r][1], o[r][2], o[r][3]);
            *(float4*)&V[(size_t)(i * 64 + ty * 4 + r) * DD + j * 64 + tx * 4] = v;
            if (i < 3) *(float4*)&sV[(i - j) * 64 * 68 + (ty * 4 + r) * 68 + tx * 4] = v;
        }
        __syncthreads();
    }
}

// ---------------------------------------------------------------------------
// Kernel 4a: out[b][s] = -0.5*(D*log2pi + logdet[s])   (base for atomic maha)
// ---------------------------------------------------------------------------
__global__ __launch_bounds__(256) void init_out_kernel(float* __restrict__ out) {
    const float log2pi = 1.8378770664093453f;
    int b = blockIdx.x, s = threadIdx.x;
    out[(size_t)b * SS + s] = -0.5f * ((float)DD * log2pi + d_logdet[s]);
}

// ---------------------------------------------------------------------------
// Kernel 4b: mma.sync bf16-split GEMM  Z = Linv_half * Diff^T, maha += colsum(Z^2)
// grid (btile=8, half=2, s=256), 256 thr = 8 warps, warp tile 32(m) x 64(n).
// smem: 4 bf16 planes [128][72] = 73728 B (Ahi, Alo, Bhi, Blo).
// ---------------------------------------------------------------------------
#define LDA 72
__global__ __launch_bounds__(256) void mahaZ_kernel(const float* __restrict__ x,
                                                    const float* __restrict__ mu,
                                                    float* __restrict__ out) {
    extern __shared__ __nv_bfloat16 smh[];
    const uint32_t sbase = smem_u32(smh);
    const int tid = threadIdx.x, wid = tid >> 5, lane = tid & 31;
    const int wm = wid & 3, wn = wid >> 2;
    const int b0 = blockIdx.x * 128, h = blockIdx.y, s = blockIdx.z;
    const int nchunks = 2 * (h + 1);

    const uint32_t AHI = 0, ALO = 128 * LDA, BHI = 2 * 128 * LDA, BLO = 3 * 128 * LDA;

    const float* Asrc = d_Linv + ((size_t)s * DD + h * 128) * DD;
    const float* Bsrc = x + (size_t)b0 * DD;
    const float* msrc = mu + (size_t)s * DD;

    float acc[2][8][4];
#pragma unroll
    for (int i = 0; i < 2; i++)
#pragma unroll
        for (int j = 0; j < 8; j++)
#pragma unroll
            for (int r = 0; r < 4; r++) acc[i][j][r] = 0.f;

    const uint32_t aRow = wm * 32 + (lane & 15);
    const uint32_t aColOff = ((lane >> 4) << 3);
    const uint32_t bRow = wn * 64 + (lane & 7) + ((lane >> 4) << 3);
    const uint32_t bColOff = (((lane >> 3) & 1) << 3);

    for (int c = 0; c < nchunks; c++) {
        const int k0 = c * 64;
        for (int idx = tid; idx < 2048; idx += 256) {
            int row = idx >> 4, q = idx & 15;
            uint2 hi, lo;
            {
                float4 v = *(const float4*)(Asrc + (size_t)row * DD + k0 + q * 4);
                cvt_split(v, hi, lo);
                *(uint2*)(smh + AHI + row * LDA + q * 4) = hi;
                *(uint2*)(smh + ALO + row * LDA + q * 4) = lo;
            }
            {
                float4 v = *(const float4*)(Bsrc + (size_t)row * DD + k0 + q * 4);
                float4 m4 = *(const float4*)(msrc + k0 + q * 4);
                v.x -= m4.x; v.y -= m4.y; v.z -= m4.z; v.w -= m4.w;
                cvt_split(v, hi, lo);
                *(uint2*)(smh + BHI + row * LDA + q * 4) = hi;
                *(uint2*)(smh + BLO + row * LDA + q * 4) = lo;
            }
        }
        __syncthreads();
#pragma unroll
        for (int ks = 0; ks < 4; ks++) {
            const uint32_t kc = ks * 16;
            uint32_t ahi[2][4], alo[2][4];
#pragma unroll
            for (int i = 0; i < 2; i++) {
                uint32_t ra = (aRow + i * 16) * LDA + kc + aColOff;
                ldsm_x4(ahi[i][0], ahi[i][1], ahi[i][2], ahi[i][3], sbase + (AHI + ra) * 2);
                ldsm_x4(alo[i][0], alo[i][1], alo[i][2], alo[i][3], sbase + (ALO + ra) * 2);
            }
#pragma unroll
            for (int p = 0; p < 4; p++) {
                uint32_t bhi[4], blo[4];
                uint32_t rb = (bRow + p * 16) * LDA + kc + bColOff;
                ldsm_x4(bhi[0], bhi[1], bhi[2], bhi[3], sbase + (BHI + rb) * 2);
                ldsm_x4(blo[0], blo[1], blo[2], blo[3], sbase + (BLO + rb) * 2);
#pragma unroll
                for (int i = 0; i < 2; i++) {
                    mma_bf16(acc[i][2 * p + 0], ahi[i], bhi[0], bhi[1]);
                    mma_bf16(acc[i][2 * p + 1], ahi[i], bhi[2], bhi[3]);
                    mma_bf16(acc[i][2 * p + 0], ahi[i], blo[0], blo[1]);
                    mma_bf16(acc[i][2 * p + 1], ahi[i], blo[2], blo[3]);
                    mma_bf16(acc[i][2 * p + 0], alo[i], bhi[0], bhi[1]);
                    mma_bf16(acc[i][2 * p + 1], alo[i], bhi[2], bhi[3]);
                }
            }
        }
        __syncthreads();
    }

    float* sRed = (float*)smh;   // [8][64]
    float cs0[8], cs1[8];
#pragma unroll
    for (int j = 0; j < 8; j++) {
        float s0 = 0.f, s1 = 0.f;
#pragma unroll
        for (int i = 0; i < 2; i++) {
            s0 += acc[i][j][0] * acc[i][j][0] + acc[i][j][2] * acc[i][j][2];
            s1 += acc[i][j][1] * acc[i][j][1] + acc[i][j][3] * acc[i][j][3];
        }
#pragma unroll
        for (int o = 4; o <= 16; o <<= 1) {
            s0 += __shfl_xor_sync(0xFFFFFFFF, s0, o);
            s1 += __shfl_xor_sync(0xFFFFFFFF, s1, o);
        }
        cs0[j] = s0; cs1[j] = s1;
    }
    if (lane < 4) {
#pragma unroll
        for (int j = 0; j < 8; j++) {
            sRed[wid * 64 + j * 8 + 2 * lane + 0] = cs0[j];
            sRed[wid * 64 + j * 8 + 2 * lane + 1] = cs1[j];
        }
    }
    __syncthreads();
    if (tid < 128) {
        int nn = tid & 63, g = (tid >> 6) * 4;
        float m = sRed[(g + 0) * 64 + nn] + sRed[(g + 1) * 64 + nn]
                + sRed[(g + 2) * 64 + nn] + sRed[(g + 3) * 64 + nn];
        atomicAdd(&out[(size_t)(b0 + tid) * SS + s], -0.5f * m);
    }
}

// ---------------------------------------------------------------------------
extern "C" void kernel_launch(void* const* d_in, const int* in_sizes, int n_in,
                              void* d_out, int out_size) {
    const float* x  = (const float*)d_in[0];   // (1024, 256)
    const float* mu = (const float*)d_in[1];   // (256, 1, 256)
    const float* sg = (const float*)d_in[2];   // (256, 1, 256, 256)
    float* out = (float*)d_out;                // (1024, 256)

    cudaFuncSetAttribute(syrk_kernel,  cudaFuncAttributeMaxDynamicSharedMemorySize, 67584);
    cudaFuncSetAttribute(chol_kernel,  cudaFuncAttributeMaxDynamicSharedMemorySize, 83200);
    cudaFuncSetAttribute(linv_kernel,  cudaFuncAttributeMaxDynamicSharedMemorySize, 87040);
    cudaFuncSetAttribute(mahaZ_kernel, cudaFuncAttributeMaxDynamicSharedMemorySize, 73728);

    ridge_kernel<<<SS, 256>>>(sg);
    syrk_kernel<<<dim3(3, SS), 256, 67584>>>(sg);
    chol_kernel<<<SS, 256, 83200>>>();
    linv_kernel<<<dim3(SS, 3), 256, 87040>>>();
    init_out_kernel<<<1024, 256>>>(out);
    mahaZ_kernel<<<dim3(8, 2, SS), 256, 73728>>>(x, mu, out);
}

// round 13
// speedup vs baseline: 3.4593x; 1.2056x over previous
#include <cuda_runtime.h>
#include <cuda_bf16.h>
#include <math.h>
#include <stdint.h>

#define DD 256
#define SS 256
#define NB 64

// Scratch (device globals; no allocation allowed)
__device__ float d_L[(size_t)SS * DD * DD];            // 64 MB: Sigma -> L (lower valid)
__device__ float d_Linv[(size_t)SS * DD * DD];         // 64 MB: explicit L^-1 (block lower; (0,1),(2,3) zeroed)
__device__ float d_invDiag[(size_t)SS * 4 * NB * NB];  // inv of diag 64x64 blocks
__device__ float d_ridge[SS];
__device__ float d_logdet[SS];

// ======================= PTX helpers (sm_80-level only) =======================
__device__ __forceinline__ uint32_t smem_u32(const void* p) {
    uint32_t a;
    asm("{ .reg .u64 t; cvta.to.shared.u64 t, %1; cvt.u32.u64 %0, t; }" : "=r"(a) : "l"(p));
    return a;
}
__device__ __forceinline__ void ldsm_x4(uint32_t& r0, uint32_t& r1, uint32_t& r2, uint32_t& r3,
                                        uint32_t addr) {
    asm volatile("ldmatrix.sync.aligned.m8n8.x4.shared.b16 {%0,%1,%2,%3}, [%4];"
                 : "=r"(r0), "=r"(r1), "=r"(r2), "=r"(r3) : "r"(addr));
}
__device__ __forceinline__ void ldsm_x4t(uint32_t& r0, uint32_t& r1, uint32_t& r2, uint32_t& r3,
                                         uint32_t addr) {
    asm volatile("ldmatrix.sync.aligned.m8n8.x4.trans.shared.b16 {%0,%1,%2,%3}, [%4];"
                 : "=r"(r0), "=r"(r1), "=r"(r2), "=r"(r3) : "r"(addr));
}
__device__ __forceinline__ void mma_bf16(float* d, const uint32_t* a, uint32_t b0, uint32_t b1) {
    asm volatile("mma.sync.aligned.m16n8k16.row.col.f32.bf16.bf16.f32 "
                 "{%0,%1,%2,%3}, {%4,%5,%6,%7}, {%8,%9}, {%0,%1,%2,%3};"
                 : "+f"(d[0]), "+f"(d[1]), "+f"(d[2]), "+f"(d[3])
                 : "r"(a[0]), "r"(a[1]), "r"(a[2]), "r"(a[3]), "r"(b0), "r"(b1));
}
__device__ __forceinline__ void cvt_split(float4 v, uint2& hi, uint2& lo) {
    __nv_bfloat16 h0 = __float2bfloat16(v.x), h1 = __float2bfloat16(v.y),
                  h2 = __float2bfloat16(v.z), h3 = __float2bfloat16(v.w);
    __nv_bfloat16 l0 = __float2bfloat16(v.x - __bfloat162float(h0));
    __nv_bfloat16 l1 = __float2bfloat16(v.y - __bfloat162float(h1));
    __nv_bfloat16 l2 = __float2bfloat16(v.z - __bfloat162float(h2));
    __nv_bfloat16 l3 = __float2bfloat16(v.w - __bfloat162float(h3));
    __nv_bfloat162 ph0 = __halves2bfloat162(h0, h1), ph1 = __halves2bfloat162(h2, h3);
    __nv_bfloat162 pl0 = __halves2bfloat162(l0, l1), pl1 = __halves2bfloat162(l2, l3);
    hi.x = *(uint32_t*)&ph0; hi.y = *(uint32_t*)&ph1;
    lo.x = *(uint32_t*)&pl0; lo.y = *(uint32_t*)&pl1;
}

// ---------------------------------------------------------------------------
// Kernel 1: ridge[s] = 0.01 * ||sp_s||_F^2 / D
// ---------------------------------------------------------------------------
__global__ __launch_bounds__(256) void ridge_kernel(const float* __restrict__ sp) {
    const int s = blockIdx.x;
    const float* A = sp + (size_t)s * DD * DD;
    float acc = 0.f;
    for (int i = threadIdx.x; i < DD * DD; i += 256) { float v = A[i]; acc += v * v; }
    __shared__ float red[256];
    red[threadIdx.x] = acc; __syncthreads();
    for (int o = 128; o > 0; o >>= 1) {
        if (threadIdx.x < o) red[threadIdx.x] += red[threadIdx.x + o];
        __syncthreads();
    }
    if (threadIdx.x == 0) d_ridge[s] = 0.01f * red[0] / (float)DD;
}

// ---------------------------------------------------------------------------
// Kernel 2: Sigma_s = sp^T sp + ridge*I via mma.sync bf16-split.
// grid (3 tiles of 128x128: (0,0),(1,0),(1,1), s). Diagonal tiles stage only
// their 128-wide d slice (half the staging of off-diag).
// smem = 2 * 64*264 * 2B = 67584 B.
// ---------------------------------------------------------------------------
#define SLDK 264
__global__ __launch_bounds__(256) void syrk_kernel(const float* __restrict__ sp) {
    extern __shared__ __nv_bfloat16 smh[];
    const uint32_t sbase = smem_u32(smh);
    const uint32_t LO = 64 * SLDK;   // elem offset of lo plane
    const int t = blockIdx.x;
    const int ti = (t + 1) >> 1, tj = t >> 1;   // (0,0),(1,0),(1,1)
    const int s = blockIdx.y;
    const float* A = sp + (size_t)s * DD * DD;
    float* C = d_L + (size_t)s * DD * DD;

    const int tid = threadIdx.x, wid = tid >> 5, lane = tid & 31;
    const int wm = wid & 3, wn = wid >> 2;
    const int dlo = (ti == tj) ? ti * 128 : 0;       // staged d-range start
    const int dw  = (ti == tj) ? 128 : 256;          // staged width
    const int gm0 = ti * 128 + wm * 32, gn0 = tj * 128 + wn * 64;   // global
    const int lm0 = gm0 - dlo, ln0 = gn0 - dlo;                     // smem-local

    const int lt = lane >> 3, lr = lane & 7;
    const uint32_t aK = lr + 8 * (lt >> 1), aM = 8 * (lt & 1);   // A frag lane map
    const uint32_t bK = lr + 8 * (lt & 1),  bN = 8 * (lt >> 1);  // B frag lane map

    float acc[2][8][4];
#pragma unroll
    for (int i = 0; i < 2; i++)
#pragma unroll
        for (int j = 0; j < 8; j++)
#pragma unroll
            for (int r = 0; r < 4; r++) acc[i][j][r] = 0.f;

    for (int k0 = 0; k0 < DD; k0 += 64) {
        // stage [64 k][dw d] hi/lo
        for (int idx = tid; idx < 16 * dw; idx += 256) {
            int k = idx / (dw >> 2), dq = (idx % (dw >> 2)) << 2;
            float4 v = *(const float4*)(A + (size_t)(k0 + k) * DD + dlo + dq);
            uint2 hi, lo; cvt_split(v, hi, lo);
            *(uint2*)(smh + k * SLDK + dq) = hi;
            *(uint2*)(smh + LO + k * SLDK + dq) = lo;
        }
        __syncthreads();
#pragma unroll
        for (int ks = 0; ks < 4; ks++) {
            const uint32_t kc = ks * 16;
            uint32_t ahi[2][4], alo[2][4];
#pragma unroll
            for (int i = 0; i < 2; i++) {
                uint32_t ra = (kc + aK) * SLDK + lm0 + i * 16 + aM;
                ldsm_x4t(ahi[i][0], ahi[i][1], ahi[i][2], ahi[i][3], sbase + ra * 2);
                ldsm_x4t(alo[i][0], alo[i][1], alo[i][2], alo[i][3], sbase + (LO + ra) * 2);
            }
#pragma unroll
            for (int p = 0; p < 4; p++) {
                uint32_t bhi[4], blo[4];
                uint32_t rb = (kc + bK) * SLDK + ln0 + p * 16 + bN;
                ldsm_x4t(bhi[0], bhi[1], bhi[2], bhi[3], sbase + rb * 2);
                ldsm_x4t(blo[0], blo[1], blo[2], blo[3], sbase + (LO + rb) * 2);
#pragma unroll
                for (int i = 0; i < 2; i++) {
                    mma_bf16(acc[i][2 * p + 0], ahi[i], bhi[0], bhi[1]);
                    mma_bf16(acc[i][2 * p + 1], ahi[i], bhi[2], bhi[3]);
                    mma_bf16(acc[i][2 * p + 0], ahi[i], blo[0], blo[1]);
                    mma_bf16(acc[i][2 * p + 1], ahi[i], blo[2], blo[3]);
                    mma_bf16(acc[i][2 * p + 0], alo[i], bhi[0], bhi[1]);
                    mma_bf16(acc[i][2 * p + 1], alo[i], bhi[2], bhi[3]);
                }
            }
        }
        __syncthreads();
    }

    // epilogue: += ridge on exact diagonal, write fp32 C
    const float ridge = d_ridge[s];
    const int crow = lane >> 2, ccol = 2 * (lane & 3);
#pragma unroll
    for (int i = 0; i < 2; i++)
#pragma unroll
        for (int j = 0; j < 8; j++) {
            int row = gm0 + i * 16 + crow;
            int col = gn0 + j * 8 + ccol;
            float c0 = acc[i][j][0], c1 = acc[i][j][1], c2 = acc[i][j][2], c3 = acc[i][j][3];
            if (row == col) c0 += ridge;
            if (row == col + 1) c1 += ridge;
            if (row + 8 == col) c2 += ridge;
            if (row + 8 == col + 1) c3 += ridge;
            *(float2*)&C[(size_t)row * DD + col] = make_float2(c0, c1);
            *(float2*)&C[(size_t)(row + 8) * DD + col] = make_float2(c2, c3);
        }
}

// ---------------------------------------------------------------------------
// Kernel 3: per-s blocked Cholesky. NEW: serial factor only on the 64x64 diag
// block; invD via forward solve; L21 = A21 * invD^T as a parallel GEMM;
// trailing update as before. smem = (256*65 + 64*68)*4 = 83968 B.
// ---------------------------------------------------------------------------
__global__ __launch_bounds__(256) void chol_kernel() {
    extern __shared__ float sm[];
    float* sP = sm;               // 256*65 panel
    float* sI = sm + 256 * 65;    // 64*68 invD (68 pitch: float4-aligned rows)
    __shared__ float sLd;
    const int s = blockIdx.x;
    const int tid = threadIdx.x;
    const int tx = tid & 15, ty = tid >> 4;
    float* L = d_L + (size_t)s * DD * DD;
    if (tid == 0) sLd = 0.f;

    for (int p = 0; p < 4; p++) {
        const int r0 = p * NB;
        const int nrows = DD - r0;
        // load full panel A (rows r0..255, cols p-block)
        for (int idx = tid; idx < nrows * NB; idx += 256)
            sP[(idx >> 6) * 65 + (idx & 63)] = L[(size_t)(r0 + (idx >> 6)) * DD + r0 + (idx & 63)];
        __syncthreads();

        // factor ONLY the 64x64 diag block (diag kept unsqrt'd in-loop)
        for (int j = 0; j < NB; j++) {
            float dj = sP[j * 65 + j];
            float rs = 1.0f / sqrtf(dj);
            if (tid == 0) sLd += logf(dj);
            if (tid > j && tid < NB) sP[tid * 65 + j] *= rs;
            __syncthreads();
            int c = j + 1 + (tid & 63);
            if (c < NB) {
                float lc = sP[c * 65 + j];
                for (int r = j + 1 + (tid >> 6); r < NB; r += 4)
                    sP[r * 65 + c] -= sP[r * 65 + j] * lc;
            }
            __syncthreads();
        }
        if (tid < NB) sP[tid * 65 + tid] = sqrtf(sP[tid * 65 + tid]);
        __syncthreads();

        // invD of diag block (64-thread forward solve per column)
        if (tid < NB) {
            int c = tid;
            for (int r = 0; r < NB; r++) {
                float v = (r == c) ? 1.f : 0.f;
                for (int k = c; k < r; k++) v -= sP[r * 65 + k] * sI[k * 68 + c];
                sI[r * 68 + c] = (r < c) ? 0.f : v / sP[r * 65 + r];
            }
        }
        __syncthreads();
        for (int idx = tid; idx < NB * NB; idx += 256)
            d_invDiag[((size_t)s * 4 + p) * (NB * NB) + idx] = sI[(idx >> 6) * 68 + (idx & 63)];

        // L21 blocks: L21 = A21 * invD^T  (rows 64.., in-place in sP)
        const int nq = (nrows >> 6) - 1;
        for (int q = 1; q <= nq; q++) {
            const int rb = q * 64;
            float a[4][4];
#pragma unroll
            for (int r = 0; r < 4; r++)
#pragma unroll
                for (int c = 0; c < 4; c++) a[r][c] = 0.f;
#pragma unroll 4
            for (int k = 0; k < NB; k++) {
                float p0 = sP[(rb + ty * 4 + 0) * 65 + k];
                float p1 = sP[(rb + ty * 4 + 1) * 65 + k];
                float p2 = sP[(rb + ty * 4 + 2) * 65 + k];
                float p3 = sP[(rb + ty * 4 + 3) * 65 + k];
                float i0 = sI[(tx * 4 + 0) * 68 + k];
                float i1 = sI[(tx * 4 + 1) * 68 + k];
                float i2 = sI[(tx * 4 + 2) * 68 + k];
                float i3 = sI[(tx * 4 + 3) * 68 + k];
                a[0][0] += p0 * i0; a[0][1] += p0 * i1; a[0][2] += p0 * i2; a[0][3] += p0 * i3;
                a[1][0] += p1 * i0; a[1][1] += p1 * i1; a[1][2] += p1 * i2; a[1][3] += p1 * i3;
                a[2][0] += p2 * i0; a[2][1] += p2 * i1; a[2][2] += p2 * i2; a[2][3] += p2 * i3;
                a[3][0] += p3 * i0; a[3][1] += p3 * i1; a[3][2] += p3 * i2; a[3][3] += p3 * i3;
            }
            __syncthreads();      // all reads of A21 block done
#pragma unroll
            for (int r = 0; r < 4; r++)
#pragma unroll
                for (int c = 0; c < 4; c++)
                    sP[(rb + ty * 4 + r) * 65 + tx * 4 + c] = a[r][c];
        }
        __syncthreads();

        // write panel back as L
        for (int idx = tid; idx < nrows * NB; idx += 256)
            L[(size_t)(r0 + (idx >> 6)) * DD + r0 + (idx & 63)] = sP[(idx >> 6) * 65 + (idx & 63)];

        // trailing update in gmem: Trail -= L21 L21^T
        const int nt = 3 - p;
        for (int ti2 = 0; ti2 < nt; ti2++)
            for (int tj2 = 0; tj2 < nt; tj2++) {
                int lr = NB + ti2 * NB + ty * 4;
                int lc = NB + tj2 * NB + tx * 4;
                float accm[4][4];
#pragma unroll
                for (int r = 0; r < 4; r++) {
                    float4 v = *(float4*)&L[(size_t)(r0 + lr + r) * DD + r0 + lc];
                    accm[r][0] = v.x; accm[r][1] = v.y; accm[r][2] = v.z; accm[r][3] = v.w;
                }
#pragma unroll 4
                for (int k = 0; k < NB; k++) {
                    float a0 = sP[(lr + 0) * 65 + k];
                    float a1 = sP[(lr + 1) * 65 + k];
                    float a2 = sP[(lr + 2) * 65 + k];
                    float a3 = sP[(lr + 3) * 65 + k];
                    float b0 = sP[(lc + 0) * 65 + k];
                    float b1 = sP[(lc + 1) * 65 + k];
                    float b2 = sP[(lc + 2) * 65 + k];
                    float b3 = sP[(lc + 3) * 65 + k];
                    accm[0][0] -= a0 * b0; accm[0][1] -= a0 * b1; accm[0][2] -= a0 * b2; accm[0][3] -= a0 * b3;
                    accm[1][0] -= a1 * b0; accm[1][1] -= a1 * b1; accm[1][2] -= a1 * b2; accm[1][3] -= a1 * b3;
                    accm[2][0] -= a2 * b0; accm[2][1] -= a2 * b1; accm[2][2] -= a2 * b2; accm[2][3] -= a2 * b3;
                    accm[3][0] -= a3 * b0; accm[3][1] -= a3 * b1; accm[3][2] -= a3 * b2; accm[3][3] -= a3 * b3;
                }
#pragma unroll
                for (int r = 0; r < 4; r++) {
                    float4 v = make_float4(accm[r][0], accm[r][1], accm[r][2], accm[r][3]);
                    *(float4*)&L[(size_t)(r0 + lr + r) * DD + r0 + lc] = v;
                }
            }
        __syncthreads();  // sP reads done before next panel load
    }
    if (tid == 0) d_logdet[s] = sLd;
}

// ---------------------------------------------------------------------------
// Kernel 3b: explicit Linv, column-parallel with register double-buffer
// prefetch of L blocks / invD (hides gmem latency between chain GEMMs).
// dyn smem = 6 * 64*68 * 4 = 104448 B (sV[3], sL2[2], sM).
// ---------------------------------------------------------------------------
__global__ __launch_bounds__(256) void linv_kernel() {
    extern __shared__ float sm[];
    float* sV  = sm;                     // [3][64*68]
    float* sL2 = sm + 3 * 4352;          // [2][64*68] ping-pong
    float* sM  = sm + 5 * 4352;          // [64*68]
    const int s = blockIdx.x, j = blockIdx.y;
    const int tid = threadIdx.x, tx = tid & 15, ty = tid >> 4;
    const float* L = d_L + (size_t)s * DD * DD;
    const float* ID = d_invDiag + (size_t)s * 4 * (NB * NB);
    float* V = d_Linv + (size_t)s * DD * DD;

    // seed chain with invD_j; write diag block j; extra duties
    for (int idx = tid; idx < NB * NB; idx += 256) {
        int rr = idx >> 6, cc = idx & 63;
        float v = ID[j * NB * NB + idx];
        sV[rr * 68 + cc] = v;
        V[(size_t)(j * 64 + rr) * DD + j * 64 + cc] = v;
        if (j == 0) V[(size_t)rr * DD + 64 + cc] = 0.f;
        if (j == 1) V[(size_t)(128 + rr) * DD + 192 + cc] = 0.f;
        if (j == 2) V[(size_t)(192 + rr) * DD + 192 + cc] = ID[3 * NB * NB + idx];
    }
    __syncthreads();

    // prefetch first L block (i=j+1, k=j): 16 floats/thread
    const int pr = tid >> 2, pc = (tid & 3) << 4;
    float4 pf[4];
#pragma unroll
    for (int q = 0; q < 4; q++)
        pf[q] = *(const float4*)&L[(size_t)((j + 1) * 64 + pr) * DD + j * 64 + pc + q * 4];

    for (int i = j + 1; i < 4; i++) {
        float acc[4][4];
#pragma unroll
        for (int r = 0; r < 4; r++)
#pragma unroll
            for (int c = 0; c < 4; c++) acc[r][c] = 0.f;

        for (int k = j; k < i; k++) {
            float* sLb = sL2 + ((k - j) & 1) * 4352;
#pragma unroll
            for (int q = 0; q < 4; q++) *(float4*)&sLb[pr * 68 + pc + q * 4] = pf[q];
            __syncthreads();
            // prefetch next block (or invD_i on last k) — latency hidden by compute
            if (k + 1 < i) {
#pragma unroll
                for (int q = 0; q < 4; q++)
                    pf[q] = *(const float4*)&L[(size_t)(i * 64 + pr) * DD + (k + 1) * 64 + pc + q * 4];
            } else {
#pragma unroll
                for (int q = 0; q < 4; q++)
                    pf[q] = *(const float4*)&ID[(size_t)i * NB * NB + pr * 64 + pc + q * 4];
            }
            const float* Vb = sV + (k - j) * 4352;
#pragma unroll 4
            for (int kk = 0; kk < 64; kk++) {
                float a0 = sLb[(ty * 4 + 0) * 68 + kk];
                float a1 = sLb[(ty * 4 + 1) * 68 + kk];
                float a2 = sLb[(ty * 4 + 2) * 68 + kk];
                float a3 = sLb[(ty * 4 + 3) * 68 + kk];
                float4 b = *(const float4*)&Vb[kk * 68 + tx * 4];
                acc[0][0] += a0 * b.x; acc[0][1] += a0 * b.y; acc[0][2] += a0 * b.z; acc[0][3] += a0 * b.w;
                acc[1][0] += a1 * b.x; acc[1][1] += a1 * b.y; acc[1][2] += a1 * b.z; acc[1][3] += a1 * b.w;
                acc[2][0] += a2 * b.x; acc[2][1] += a2 * b.y; acc[2][2] += a2 * b.z; acc[2][3] += a2 * b.w;
                acc[3][0] += a3 * b.x; acc[3][1] += a3 * b.y; acc[3][2] += a3 * b.z; acc[3][3] += a3 * b.w;
            }
            // no sync: next store targets the other buffer
        }

        // stage invD_i (prefetched) and the accumulated M
        const int b2 = (i - j) & 1;
        float* sLb2 = sL2 + b2 * 4352;
#pragma unroll
        for (int q = 0; q < 4; q++) *(float4*)&sLb2[pr * 68 + pc + q * 4] = pf[q];
#pragma unroll
        for (int r = 0; r < 4; r++)
#pragma unroll
            for (int c = 0; c < 4; c++) sM[(ty * 4 + r) * 68 + tx * 4 + c] = acc[r][c];
        __syncthreads();
        // prefetch next i's first block
        if (i < 3) {
#pragma unroll
            for (int q = 0; q < 4; q++)
                pf[q] = *(const float4*)&L[(size_t)((i + 1) * 64 + pr) * DD + j * 64 + pc + q * 4];
        }
        // o = -invD_i * M
        float o[4][4];
#pragma unroll
        for (int r = 0; r < 4; r++)
#pragma unroll
            for (int c = 0; c < 4; c++) o[r][c] = 0.f;
#pragma unroll 4
        for (int kk = 0; kk < 64; kk++) {
            float a0 = sLb2[(ty * 4 + 0) * 68 + kk];
            float a1 = sLb2[(ty * 4 + 1) * 68 + kk];
            float a2 = sLb2[(ty * 4 + 2) * 68 + kk];
            float a3 = sLb2[(ty * 4 + 3) * 68 + kk];
            float4 b = *(const float4*)&sM[kk * 68 + tx * 4];
            o[0][0] -= a0 * b.x; o[0][1] -= a0 * b.y; o[0][2] -= a0 * b.z; o[0][3] -= a0 * b.w;
            o[1][0] -= a1 * b.x; o[1][1] -= a1 * b.y; o[1][2] -= a1 * b.z; o[1][3] -= a1 * b.w;
            o[2][0] -= a2 * b.x; o[2][1] -= a2 * b.y; o[2][2] -= a2 * b.z; o[2][3] -= a2 * b.w;
            o[3][0] -= a3 * b.x; o[3][1] -= a3 * b.y; o[3][2] -= a3 * b.z; o[3][3] -= a3 * b.w;
        }
        __syncthreads();   // sLb2/sM reads done before reuse; orders sV write below
#pragma unroll
        for (int r = 0; r < 4; r++) {
            float4 v = make_float4(o[r][0], o[r][1], o[r][2], o[r][3]);
            *(float4*)&V[(size_t)(i * 64 + ty * 4 + r) * DD + j * 64 + tx * 4] = v;
            if (i < 3) *(float4*)&sV[(i - j) * 4352 + (ty * 4 + r) * 68 + tx * 4] = v;
        }
        __syncthreads();
    }
}

// ---------------------------------------------------------------------------
// Kernel 4a: out[b][s] = -0.5*(D*log2pi + logdet[s])   (base for atomic maha)
// ---------------------------------------------------------------------------
__global__ __launch_bounds__(256) void init_out_kernel(float* __restrict__ out) {
    const float log2pi = 1.8378770664093453f;
    int b = blockIdx.x, s = threadIdx.x;
    out[(size_t)b * SS + s] = -0.5f * ((float)DD * log2pi + d_logdet[s]);
}

// ---------------------------------------------------------------------------
// Kernel 4b: mma.sync bf16-split GEMM  Z = Linv_half * Diff^T, maha += colsum(Z^2)
// grid (btile=8, half=2, s=256), 256 thr = 8 warps, warp tile 32(m) x 64(n).
// smem: 4 bf16 planes [128][72] = 73728 B (Ahi, Alo, Bhi, Blo).
// ---------------------------------------------------------------------------
#define LDA 72
__global__ __launch_bounds__(256) void mahaZ_kernel(const float* __restrict__ x,
                                                    const float* __restrict__ mu,
                                                    float* __restrict__ out) {
    extern __shared__ __nv_bfloat16 smh[];
    const uint32_t sbase = smem_u32(smh);
    const int tid = threadIdx.x, wid = tid >> 5, lane = tid & 31;
    const int wm = wid & 3, wn = wid >> 2;
    const int b0 = blockIdx.x * 128, h = blockIdx.y, s = blockIdx.z;
    const int nchunks = 2 * (h + 1);

    const uint32_t AHI = 0, ALO = 128 * LDA, BHI = 2 * 128 * LDA, BLO = 3 * 128 * LDA;

    const float* Asrc = d_Linv + ((size_t)s * DD + h * 128) * DD;
    const float* Bsrc = x + (size_t)b0 * DD;
    const float* msrc = mu + (size_t)s * DD;

    float acc[2][8][4];
#pragma unroll
    for (int i = 0; i < 2; i++)
#pragma unroll
        for (int j = 0; j < 8; j++)
#pragma unroll
            for (int r = 0; r < 4; r++) acc[i][j][r] = 0.f;

    const uint32_t aRow = wm * 32 + (lane & 15);
    const uint32_t aColOff = ((lane >> 4) << 3);
    const uint32_t bRow = wn * 64 + (lane & 7) + ((lane >> 4) << 3);
    const uint32_t bColOff = (((lane >> 3) & 1) << 3);

    for (int c = 0; c < nchunks; c++) {
        const int k0 = c * 64;
        for (int idx = tid; idx < 2048; idx += 256) {
            int row = idx >> 4, q = idx & 15;
            uint2 hi, lo;
            {
                float4 v = *(const float4*)(Asrc + (size_t)row * DD + k0 + q * 4);
                cvt_split(v, hi, lo);
                *(uint2*)(smh + AHI + row * LDA + q * 4) = hi;
                *(uint2*)(smh + ALO + row * LDA + q * 4) = lo;
            }
            {
                float4 v = *(const float4*)(Bsrc + (size_t)row * DD + k0 + q * 4);
                float4 m4 = *(const float4*)(msrc + k0 + q * 4);
                v.x -= m4.x; v.y -= m4.y; v.z -= m4.z; v.w -= m4.w;
                cvt_split(v, hi, lo);
                *(uint2*)(smh + BHI + row * LDA + q * 4) = hi;
                *(uint2*)(smh + BLO + row * LDA + q * 4) = lo;
            }
        }
        __syncthreads();
#pragma unroll
        for (int ks = 0; ks < 4; ks++) {
            const uint32_t kc = ks * 16;
            uint32_t ahi[2][4], alo[2][4];
#pragma unroll
            for (int i = 0; i < 2; i++) {
                uint32_t ra = (aRow + i * 16) * LDA + kc + aColOff;
                ldsm_x4(ahi[i][0], ahi[i][1], ahi[i][2], ahi[i][3], sbase + (AHI + ra) * 2);
                ldsm_x4(alo[i][0], alo[i][1], alo[i][2], alo[i][3], sbase + (ALO + ra) * 2);
            }
#pragma unroll
            for (int p = 0; p < 4; p++) {
                uint32_t bhi[4], blo[4];
                uint32_t rb = (bRow + p * 16) * LDA + kc + bColOff;
                ldsm_x4(bhi[0], bhi[1], bhi[2], bhi[3], sbase + (BHI + rb) * 2);
                ldsm_x4(blo[0], blo[1], blo[2], blo[3], sbase + (BLO + rb) * 2);
#pragma unroll
                for (int i = 0; i < 2; i++) {
                    mma_bf16(acc[i][2 * p + 0], ahi[i], bhi[0], bhi[1]);
                    mma_bf16(acc[i][2 * p + 1], ahi[i], bhi[2], bhi[3]);
                    mma_bf16(acc[i][2 * p + 0], ahi[i], blo[0], blo[1]);
                    mma_bf16(acc[i][2 * p + 1], ahi[i], blo[2], blo[3]);
                    mma_bf16(acc[i][2 * p + 0], alo[i], bhi[0], bhi[1]);
                    mma_bf16(acc[i][2 * p + 1], alo[i], bhi[2], bhi[3]);
                }
            }
        }
        __syncthreads();
    }

    float* sRed = (float*)smh;   // [8][64]
    float cs0[8], cs1[8];
#pragma unroll
    for (int j = 0; j < 8; j++) {
        float s0 = 0.f, s1 = 0.f;
#pragma unroll
        for (int i = 0; i < 2; i++) {
            s0 += acc[i][j][0] * acc[i][j][0] + acc[i][j][2] * acc[i][j][2];
            s1 += acc[i][j][1] * acc[i][j][1] + acc[i][j][3] * acc[i][j][3];
        }
#pragma unroll
        for (int o = 4; o <= 16; o <<= 1) {
            s0 += __shfl_xor_sync(0xFFFFFFFF, s0, o);
            s1 += __shfl_xor_sync(0xFFFFFFFF, s1, o);
        }
        cs0[j] = s0; cs1[j] = s1;
    }
    if (lane < 4) {
#pragma unroll
        for (int j = 0; j < 8; j++) {
            sRed[wid * 64 + j * 8 + 2 * lane + 0] = cs0[j];
            sRed[wid * 64 + j * 8 + 2 * lane + 1] = cs1[j];
        }
    }
    __syncthreads();
    if (tid < 128) {
        int nn = tid & 63, g = (tid >> 6) * 4;
        float m = sRed[(g + 0) * 64 + nn] + sRed[(g + 1) * 64 + nn]
                + sRed[(g + 2) * 64 + nn] + sRed[(g + 3) * 64 + nn];
        atomicAdd(&out[(size_t)(b0 + tid) * SS + s], -0.5f * m);
    }
}

// ---------------------------------------------------------------------------
extern "C" void kernel_launch(void* const* d_in, const int* in_sizes, int n_in,
                              void* d_out, int out_size) {
    const float* x  = (const float*)d_in[0];   // (1024, 256)
    const float* mu = (const float*)d_in[1];   // (256, 1, 256)
    const float* sg = (const float*)d_in[2];   // (256, 1, 256, 256)
    float* out = (float*)d_out;                // (1024, 256)

    cudaFuncSetAttribute(syrk_kernel,  cudaFuncAttributeMaxDynamicSharedMemorySize, 67584);
    cudaFuncSetAttribute(chol_kernel,  cudaFuncAttributeMaxDynamicSharedMemorySize, 83968);
    cudaFuncSetAttribute(linv_kernel,  cudaFuncAttributeMaxDynamicSharedMemorySize, 104448);
    cudaFuncSetAttribute(mahaZ_kernel, cudaFuncAttributeMaxDynamicSharedMemorySize, 73728);

    ridge_kernel<<<SS, 256>>>(sg);
    syrk_kernel<<<dim3(3, SS), 256, 67584>>>(sg);
    chol_kernel<<<SS, 256, 83968>>>();
    linv_kernel<<<dim3(SS, 3), 256, 104448>>>();
    init_out_kernel<<<1024, 256>>>(out);
    mahaZ_kernel<<<dim3(8, 2, SS), 256, 73728>>>(x, mu, out);
}